// round 1
// baseline (speedup 1.0000x reference)
#include <cuda_runtime.h>
#include <cuda_bf16.h>
#include <math.h>

#define NN 50000
#define EE 800000
#define INC 256
#define HID 256
#define OUTC 128

// ---------------- scratch (static device globals; no allocation) -------------
__device__ float g_agg[(size_t)NN * HID];   // aggregation buffer (reused)
__device__ float g_hmid[(size_t)NN * HID];  // MLP hidden
__device__ float g_h1[(size_t)NN * HID];    // layer-0 output (input to layer 1)
__device__ int   g_src[EE];
__device__ int   g_dst[EE];
__device__ int   g_is64;

// ---------------- edge dtype detection + decode ------------------------------
// If edge_index is int64 (little-endian, values in [0, 50000)), every odd
// 32-bit word is 0. For int32 data the odd words are random edge ids; the
// probability all 32 sampled words are 0 is (1/50000)^32 ~ 0.
__global__ void detect_k(const unsigned int* __restrict__ ei) {
    unsigned v = ei[threadIdx.x * 2 + 1];
    unsigned nz = __ballot_sync(0xFFFFFFFFu, v != 0u);
    if (threadIdx.x == 0) g_is64 = (nz == 0u) ? 1 : 0;
}

__global__ void decode_k(const void* __restrict__ ei, int E) {
    int i = blockIdx.x * blockDim.x + threadIdx.x;
    if (i >= E) return;
    if (g_is64) {
        const long long* p = (const long long*)ei;
        g_src[i] = (int)p[i];
        g_dst[i] = (int)p[(size_t)E + i];
    } else {
        const int* p = (const int*)ei;
        g_src[i] = p[i];
        g_dst[i] = p[E + i];
    }
}

// ---------------- zero the aggregation buffer --------------------------------
__global__ void zero_agg_k() {
    size_t i = (size_t)blockIdx.x * blockDim.x + threadIdx.x;
    size_t total = (size_t)NN * HID / 4;
    if (i < total) ((float4*)g_agg)[i] = make_float4(0.f, 0.f, 0.f, 0.f);
}

// ---------------- scatter-add aggregation ------------------------------------
// thread t handles edge e = t/64, float4 chunk c = t%64 (256 feats = 64 float4)
__global__ void scatter_k(const float4* __restrict__ X, int E) {
    int t = blockIdx.x * blockDim.x + threadIdx.x;
    if (t >= E * 64) return;
    int e = t >> 6;
    int c = t & 63;
    int s = g_src[e];
    int d = g_dst[e];
    float4 v = X[(size_t)s * 64 + c];
    float* o = g_agg + (size_t)d * 256 + c * 4;
    atomicAdd(o + 0, v.x);
    atomicAdd(o + 1, v.y);
    atomicAdd(o + 2, v.z);
    atomicAdd(o + 3, v.w);
}

// ---------------- tiled fp32 GEMM, K=256 fixed -------------------------------
// C[M,Ncols] = act( Aeff[M,256] @ W[256,Ncols] + bias )
// Aeff = PREADD ? (1+*eps)*A + AGG : A
#define BM 128
#define BN 64
#define BK 16
#define TM 8
#define TN 4

template <bool PREADD, bool RELU>
__global__ __launch_bounds__(256) void gemm_k256(
    const float* __restrict__ A, const float* __restrict__ AGG,
    const float* __restrict__ eps,
    const float* __restrict__ W, const float* __restrict__ bias,
    float* __restrict__ C, int M, int Ncols)
{
    __shared__ float As[BK][BM];
    __shared__ float Bs[BK][BN];

    const int tid = threadIdx.x;
    const int blockRow = blockIdx.x * BM;
    const int blockCol = blockIdx.y * BN;
    const int tx = tid & 15;   // 16 col groups * TN=4  -> 64
    const int ty = tid >> 4;   // 16 row groups * TM=8  -> 128

    float alpha = 1.0f;
    if (PREADD) alpha = 1.0f + *eps;

    float acc[TM][TN];
#pragma unroll
    for (int i = 0; i < TM; i++)
#pragma unroll
        for (int j = 0; j < TN; j++) acc[i][j] = 0.0f;

    for (int kt = 0; kt < 256; kt += BK) {
        // --- load A tile (BM x BK) as float4, store transposed As[k][m] ---
#pragma unroll
        for (int j = 0; j < 2; j++) {
            int idx = tid * 2 + j;            // 0..511
            int r = idx >> 2;                 // 0..127
            int kc = (idx & 3) * 4;           // 0,4,8,12
            int grow = blockRow + r;
            float4 v = make_float4(0.f, 0.f, 0.f, 0.f);
            if (grow < M) {
                v = *(const float4*)(A + (size_t)grow * 256 + kt + kc);
                if (PREADD) {
                    float4 g = *(const float4*)(AGG + (size_t)grow * 256 + kt + kc);
                    v.x = fmaf(alpha, v.x, g.x);
                    v.y = fmaf(alpha, v.y, g.y);
                    v.z = fmaf(alpha, v.z, g.z);
                    v.w = fmaf(alpha, v.w, g.w);
                }
            }
            As[kc + 0][r] = v.x;
            As[kc + 1][r] = v.y;
            As[kc + 2][r] = v.z;
            As[kc + 3][r] = v.w;
        }
        // --- load B tile (BK x BN): 256 float4, one per thread ---
        {
            int r = tid >> 4;                 // 0..15
            int nc = (tid & 15) * 4;          // 0..60
            float4 v = *(const float4*)(W + (size_t)(kt + r) * Ncols + blockCol + nc);
            *(float4*)&Bs[r][nc] = v;
        }
        __syncthreads();

#pragma unroll
        for (int k = 0; k < BK; k++) {
            float a[TM], b[TN];
            const float4* ap = (const float4*)&As[k][ty * TM];
            float4 a0 = ap[0], a1 = ap[1];
            a[0] = a0.x; a[1] = a0.y; a[2] = a0.z; a[3] = a0.w;
            a[4] = a1.x; a[5] = a1.y; a[6] = a1.z; a[7] = a1.w;
            float4 b0 = *(const float4*)&Bs[k][tx * TN];
            b[0] = b0.x; b[1] = b0.y; b[2] = b0.z; b[3] = b0.w;
#pragma unroll
            for (int i = 0; i < TM; i++)
#pragma unroll
                for (int j = 0; j < TN; j++)
                    acc[i][j] = fmaf(a[i], b[j], acc[i][j]);
        }
        __syncthreads();
    }

    // --- epilogue: bias (+ relu), vectorized stores ---
    float4 bb = *(const float4*)(bias + blockCol + tx * TN);
#pragma unroll
    for (int i = 0; i < TM; i++) {
        int grow = blockRow + ty * TM + i;
        if (grow >= M) continue;
        float4 o;
        o.x = acc[i][0] + bb.x;
        o.y = acc[i][1] + bb.y;
        o.z = acc[i][2] + bb.z;
        o.w = acc[i][3] + bb.w;
        if (RELU) {
            o.x = fmaxf(o.x, 0.f);
            o.y = fmaxf(o.y, 0.f);
            o.z = fmaxf(o.z, 0.f);
            o.w = fmaxf(o.w, 0.f);
        }
        *(float4*)(C + (size_t)grow * Ncols + blockCol + tx * TN) = o;
    }
}

// ---------------- log_softmax over 128-wide rows, warp per row ---------------
__global__ void logsoftmax_k(float* __restrict__ C, int M) {
    int row = blockIdx.x * 8 + (threadIdx.x >> 5);
    int lane = threadIdx.x & 31;
    if (row >= M) return;
    float4 v = *(float4*)(C + (size_t)row * 128 + lane * 4);
    float m = fmaxf(fmaxf(v.x, v.y), fmaxf(v.z, v.w));
#pragma unroll
    for (int o = 16; o; o >>= 1) m = fmaxf(m, __shfl_xor_sync(0xFFFFFFFFu, m, o));
    float s = expf(v.x - m) + expf(v.y - m) + expf(v.z - m) + expf(v.w - m);
#pragma unroll
    for (int o = 16; o; o >>= 1) s += __shfl_xor_sync(0xFFFFFFFFu, s, o);
    float lg = m + logf(s);
    v.x -= lg; v.y -= lg; v.z -= lg; v.w -= lg;
    *(float4*)(C + (size_t)row * 128 + lane * 4) = v;
}

// ---------------- host launch -------------------------------------------------
extern "C" void kernel_launch(void* const* d_in, const int* in_sizes, int n_in,
                              void* d_out, int out_size) {
    const float* x    = (const float*)d_in[0];
    const void*  ei   = d_in[1];
    const float* eps0 = (const float*)d_in[2];
    const float* W1_0 = (const float*)d_in[3];
    const float* b1_0 = (const float*)d_in[4];
    const float* W2_0 = (const float*)d_in[5];
    const float* b2_0 = (const float*)d_in[6];
    const float* eps1 = (const float*)d_in[7];
    const float* W1_1 = (const float*)d_in[8];
    const float* b1_1 = (const float*)d_in[9];
    const float* W2_1 = (const float*)d_in[10];
    const float* b2_1 = (const float*)d_in[11];
    float* out = (float*)d_out;

    int E = in_sizes[1] / 2;
    if (E > EE) E = EE;
    int M = in_sizes[0] / INC;
    if (M > NN) M = NN;

    float* agg  = nullptr;
    float* hmid = nullptr;
    float* h1   = nullptr;
    cudaGetSymbolAddress((void**)&agg,  g_agg);
    cudaGetSymbolAddress((void**)&hmid, g_hmid);
    cudaGetSymbolAddress((void**)&h1,   g_h1);

    const int zgrid = (int)(((size_t)NN * HID / 4 + 255) / 256);
    const int sgrid = (E * 64 + 255) / 256;
    const dim3 gemm_grid_h((M + BM - 1) / BM, HID / BN);
    const dim3 gemm_grid_o((M + BM - 1) / BM, OUTC / BN);

    // edge decode (dtype-robust)
    detect_k<<<1, 32>>>((const unsigned int*)ei);
    decode_k<<<(E + 255) / 256, 256>>>(ei, E);

    // ---- layer 0 ----
    zero_agg_k<<<zgrid, 256>>>();
    scatter_k<<<sgrid, 256>>>((const float4*)x, E);
    gemm_k256<true, true><<<gemm_grid_h, 256>>>(x, agg, eps0, W1_0, b1_0, hmid, M, HID);
    gemm_k256<false, true><<<gemm_grid_h, 256>>>(hmid, nullptr, nullptr, W2_0, b2_0, h1, M, HID);

    // ---- layer 1 ----
    zero_agg_k<<<zgrid, 256>>>();
    scatter_k<<<sgrid, 256>>>((const float4*)h1, E);
    gemm_k256<true, true><<<gemm_grid_h, 256>>>(h1, agg, eps1, W1_1, b1_1, hmid, M, HID);
    gemm_k256<false, false><<<gemm_grid_o, 256>>>(hmid, nullptr, nullptr, W2_1, b2_1, out, M, OUTC);

    // ---- log_softmax ----
    logsoftmax_k<<<(M + 7) / 8, 256>>>(out, M);
}

// round 2
// speedup vs baseline: 1.9446x; 1.9446x over previous
#include <cuda_runtime.h>
#include <cuda_bf16.h>
#include <math.h>

#define NN 50000
#define EE 800000
#define INC 256
#define HID 256
#define OUTC 128

// ---------------- scratch (static device globals; no allocation) -------------
__device__ float g_hin[(size_t)NN * HID];   // fused (1+eps)*x + agg
__device__ float g_hmid[(size_t)NN * HID];  // MLP hidden
__device__ float g_h1[(size_t)NN * HID];    // layer-0 output
__device__ int   g_src[EE];
__device__ int   g_col[EE];                 // src ids sorted by dst (CSR)
__device__ int   g_deg[NN];
__device__ int   g_rowptr[NN + 1];
__device__ int   g_cursor[NN];
__device__ int   g_is64;

// ---------------- edge dtype detection ---------------------------------------
__global__ void detect_k(const unsigned int* __restrict__ ei) {
    unsigned v = ei[threadIdx.x * 2 + 1];
    unsigned nz = __ballot_sync(0xFFFFFFFFu, v != 0u);
    if (threadIdx.x == 0) g_is64 = (nz == 0u) ? 1 : 0;
}

__global__ void zero_deg_k() {
    int i = blockIdx.x * blockDim.x + threadIdx.x;
    if (i < NN) g_deg[i] = 0;
}

// decode src/dst + histogram degrees by dst
__global__ void decode_hist_k(const void* __restrict__ ei, int E) {
    int i = blockIdx.x * blockDim.x + threadIdx.x;
    if (i >= E) return;
    int s, d;
    if (g_is64) {
        const long long* p = (const long long*)ei;
        s = (int)p[i];
        d = (int)p[(size_t)E + i];
    } else {
        const int* p = (const int*)ei;
        s = p[i];
        d = p[E + i];
    }
    g_src[i] = s;
    // store dst temporarily in g_col (overwritten by fill later)
    g_col[i] = d;
    atomicAdd(&g_deg[d], 1);
}

// single-block exclusive scan over g_deg -> g_rowptr, copy to g_cursor
__global__ __launch_bounds__(1024) void scan_k(int n) {
    __shared__ int sh[1024];
    const int tid = threadIdx.x;
    const int per = (n + 1023) / 1024;
    const int base = tid * per;
    int sum = 0;
    for (int i = 0; i < per; i++)
        if (base + i < n) sum += g_deg[base + i];
    sh[tid] = sum;
    __syncthreads();
    // inclusive scan of per-thread sums
    for (int off = 1; off < 1024; off <<= 1) {
        int v = (tid >= off) ? sh[tid - off] : 0;
        __syncthreads();
        sh[tid] += v;
        __syncthreads();
    }
    int run = tid ? sh[tid - 1] : 0;
    for (int i = 0; i < per; i++) {
        int idx = base + i;
        if (idx < n) {
            g_rowptr[idx] = run;
            g_cursor[idx] = run;
            run += g_deg[idx];
        }
    }
    if (tid == 1023) g_rowptr[n] = sh[1023];
}

// fill CSR column (src) array; reads dst from g_col's temp copy... must read
// dst before overwriting -> use a separate pass reading from decode's stores.
// To avoid aliasing, fill reads dst recomputed from g_src? No: we read the
// temp dst, compute pos, then write col[pos]=src. Aliasing hazard: col[pos]
// may be a slot whose dst another thread hasn't read yet. So use a separate
// dst array instead.
__device__ int g_dst[EE];

__global__ void split_dst_k(int E) {
    int i = blockIdx.x * blockDim.x + threadIdx.x;
    if (i < E) g_dst[i] = g_col[i];
}

__global__ void fill_k(int E) {
    int i = blockIdx.x * blockDim.x + threadIdx.x;
    if (i >= E) return;
    int d = g_dst[i];
    int pos = atomicAdd(&g_cursor[d], 1);
    g_col[pos] = g_src[i];
}

// ---------------- gather aggregation: warp per node ---------------------------
// out[n] = (1+eps)*X[n] + sum_{s in nbrs(n)} X[s]
__global__ __launch_bounds__(256) void gather_k(
    const float4* __restrict__ X, const float* __restrict__ eps,
    float4* __restrict__ out, int M)
{
    int warp = (blockIdx.x * blockDim.x + threadIdx.x) >> 5;
    int lane = threadIdx.x & 31;
    if (warp >= M) return;
    const float alpha = 1.0f + *eps;

    float4 a0 = make_float4(0.f, 0.f, 0.f, 0.f);
    float4 a1 = make_float4(0.f, 0.f, 0.f, 0.f);

    int beg = g_rowptr[warp];
    int end = g_rowptr[warp + 1];
    int e = beg;
    // unroll-by-2 for MLP
    for (; e + 1 < end; e += 2) {
        int s0 = __ldg(&g_col[e]);
        int s1 = __ldg(&g_col[e + 1]);
        float4 v00 = X[(size_t)s0 * 64 + lane];
        float4 v01 = X[(size_t)s0 * 64 + 32 + lane];
        float4 v10 = X[(size_t)s1 * 64 + lane];
        float4 v11 = X[(size_t)s1 * 64 + 32 + lane];
        a0.x += v00.x + v10.x; a0.y += v00.y + v10.y;
        a0.z += v00.z + v10.z; a0.w += v00.w + v10.w;
        a1.x += v01.x + v11.x; a1.y += v01.y + v11.y;
        a1.z += v01.z + v11.z; a1.w += v01.w + v11.w;
    }
    if (e < end) {
        int s0 = __ldg(&g_col[e]);
        float4 v00 = X[(size_t)s0 * 64 + lane];
        float4 v01 = X[(size_t)s0 * 64 + 32 + lane];
        a0.x += v00.x; a0.y += v00.y; a0.z += v00.z; a0.w += v00.w;
        a1.x += v01.x; a1.y += v01.y; a1.z += v01.z; a1.w += v01.w;
    }

    float4 x0 = X[(size_t)warp * 64 + lane];
    float4 x1 = X[(size_t)warp * 64 + 32 + lane];
    a0.x = fmaf(alpha, x0.x, a0.x); a0.y = fmaf(alpha, x0.y, a0.y);
    a0.z = fmaf(alpha, x0.z, a0.z); a0.w = fmaf(alpha, x0.w, a0.w);
    a1.x = fmaf(alpha, x1.x, a1.x); a1.y = fmaf(alpha, x1.y, a1.y);
    a1.z = fmaf(alpha, x1.z, a1.z); a1.w = fmaf(alpha, x1.w, a1.w);
    out[(size_t)warp * 64 + lane] = a0;
    out[(size_t)warp * 64 + 32 + lane] = a1;
}

// ---------------- tiled fp32 GEMM, K=256 fixed -------------------------------
#define BM 128
#define BN 64
#define BK 16
#define TM 8
#define TN 4

template <bool RELU>
__global__ __launch_bounds__(256) void gemm_k256(
    const float* __restrict__ A,
    const float* __restrict__ W, const float* __restrict__ bias,
    float* __restrict__ C, int M, int Ncols)
{
    __shared__ float As[BK][BM];
    __shared__ float Bs[BK][BN];

    const int tid = threadIdx.x;
    const int blockRow = blockIdx.x * BM;
    const int blockCol = blockIdx.y * BN;
    const int tx = tid & 15;
    const int ty = tid >> 4;

    float acc[TM][TN];
#pragma unroll
    for (int i = 0; i < TM; i++)
#pragma unroll
        for (int j = 0; j < TN; j++) acc[i][j] = 0.0f;

    for (int kt = 0; kt < 256; kt += BK) {
#pragma unroll
        for (int j = 0; j < 2; j++) {
            int idx = tid * 2 + j;
            int r = idx >> 2;
            int kc = (idx & 3) * 4;
            int grow = blockRow + r;
            float4 v = make_float4(0.f, 0.f, 0.f, 0.f);
            if (grow < M)
                v = *(const float4*)(A + (size_t)grow * 256 + kt + kc);
            As[kc + 0][r] = v.x;
            As[kc + 1][r] = v.y;
            As[kc + 2][r] = v.z;
            As[kc + 3][r] = v.w;
        }
        {
            int r = tid >> 4;
            int nc = (tid & 15) * 4;
            float4 v = *(const float4*)(W + (size_t)(kt + r) * Ncols + blockCol + nc);
            *(float4*)&Bs[r][nc] = v;
        }
        __syncthreads();

#pragma unroll
        for (int k = 0; k < BK; k++) {
            float a[TM], b[TN];
            const float4* ap = (const float4*)&As[k][ty * TM];
            float4 a0 = ap[0], a1 = ap[1];
            a[0] = a0.x; a[1] = a0.y; a[2] = a0.z; a[3] = a0.w;
            a[4] = a1.x; a[5] = a1.y; a[6] = a1.z; a[7] = a1.w;
            float4 b0 = *(const float4*)&Bs[k][tx * TN];
            b[0] = b0.x; b[1] = b0.y; b[2] = b0.z; b[3] = b0.w;
#pragma unroll
            for (int i = 0; i < TM; i++)
#pragma unroll
                for (int j = 0; j < TN; j++)
                    acc[i][j] = fmaf(a[i], b[j], acc[i][j]);
        }
        __syncthreads();
    }

    float4 bb = *(const float4*)(bias + blockCol + tx * TN);
#pragma unroll
    for (int i = 0; i < TM; i++) {
        int grow = blockRow + ty * TM + i;
        if (grow >= M) continue;
        float4 o;
        o.x = acc[i][0] + bb.x;
        o.y = acc[i][1] + bb.y;
        o.z = acc[i][2] + bb.z;
        o.w = acc[i][3] + bb.w;
        if (RELU) {
            o.x = fmaxf(o.x, 0.f);
            o.y = fmaxf(o.y, 0.f);
            o.z = fmaxf(o.z, 0.f);
            o.w = fmaxf(o.w, 0.f);
        }
        *(float4*)(C + (size_t)grow * Ncols + blockCol + tx * TN) = o;
    }
}

// ---------------- log_softmax over 128-wide rows, warp per row ---------------
__global__ void logsoftmax_k(float* __restrict__ C, int M) {
    int row = blockIdx.x * 8 + (threadIdx.x >> 5);
    int lane = threadIdx.x & 31;
    if (row >= M) return;
    float4 v = *(float4*)(C + (size_t)row * 128 + lane * 4);
    float m = fmaxf(fmaxf(v.x, v.y), fmaxf(v.z, v.w));
#pragma unroll
    for (int o = 16; o; o >>= 1) m = fmaxf(m, __shfl_xor_sync(0xFFFFFFFFu, m, o));
    float s = expf(v.x - m) + expf(v.y - m) + expf(v.z - m) + expf(v.w - m);
#pragma unroll
    for (int o = 16; o; o >>= 1) s += __shfl_xor_sync(0xFFFFFFFFu, s, o);
    float lg = m + logf(s);
    v.x -= lg; v.y -= lg; v.z -= lg; v.w -= lg;
    *(float4*)(C + (size_t)row * 128 + lane * 4) = v;
}

// ---------------- host launch -------------------------------------------------
extern "C" void kernel_launch(void* const* d_in, const int* in_sizes, int n_in,
                              void* d_out, int out_size) {
    const float* x    = (const float*)d_in[0];
    const void*  ei   = d_in[1];
    const float* eps0 = (const float*)d_in[2];
    const float* W1_0 = (const float*)d_in[3];
    const float* b1_0 = (const float*)d_in[4];
    const float* W2_0 = (const float*)d_in[5];
    const float* b2_0 = (const float*)d_in[6];
    const float* eps1 = (const float*)d_in[7];
    const float* W1_1 = (const float*)d_in[8];
    const float* b1_1 = (const float*)d_in[9];
    const float* W2_1 = (const float*)d_in[10];
    const float* b2_1 = (const float*)d_in[11];
    float* out = (float*)d_out;

    int E = in_sizes[1] / 2;
    if (E > EE) E = EE;
    int M = in_sizes[0] / INC;
    if (M > NN) M = NN;

    float* hin  = nullptr;
    float* hmid = nullptr;
    float* h1   = nullptr;
    cudaGetSymbolAddress((void**)&hin,  g_hin);
    cudaGetSymbolAddress((void**)&hmid, g_hmid);
    cudaGetSymbolAddress((void**)&h1,   g_h1);

    const int egrid = (E + 255) / 256;
    const int ggrid = (M + 7) / 8;             // 8 warps (nodes) per block
    const dim3 gemm_grid_h((M + BM - 1) / BM, HID / BN);
    const dim3 gemm_grid_o((M + BM - 1) / BM, OUTC / BN);

    // ---- CSR build (per launch; graph-capturable) ----
    detect_k<<<1, 32>>>((const unsigned int*)ei);
    zero_deg_k<<<(NN + 255) / 256, 256>>>();
    decode_hist_k<<<egrid, 256>>>(ei, E);
    scan_k<<<1, 1024>>>(M);
    split_dst_k<<<egrid, 256>>>(E);
    fill_k<<<egrid, 256>>>(E);

    // ---- layer 0 ----
    gather_k<<<ggrid, 256>>>((const float4*)x, eps0, (float4*)hin, M);
    gemm_k256<true><<<gemm_grid_h, 256>>>(hin, W1_0, b1_0, hmid, M, HID);
    gemm_k256<true><<<gemm_grid_h, 256>>>(hmid, W2_0, b2_0, h1, M, HID);

    // ---- layer 1 ----
    gather_k<<<ggrid, 256>>>((const float4*)h1, eps1, (float4*)hin, M);
    gemm_k256<true><<<gemm_grid_h, 256>>>(hin, W1_1, b1_1, hmid, M, HID);
    gemm_k256<false><<<gemm_grid_o, 256>>>(hmid, W2_1, b2_1, out, M, OUTC);

    // ---- log_softmax ----
    logsoftmax_k<<<(M + 7) / 8, 256>>>(out, M);
}

// round 3
// speedup vs baseline: 2.0503x; 1.0544x over previous
#include <cuda_runtime.h>
#include <cuda_bf16.h>
#include <math.h>

#define NN 50000
#define EE 800000
#define INC 256
#define HID 256
#define OUTC 128

// ---------------- scratch (static device globals; no allocation) -------------
__device__ float g_hin[(size_t)NN * HID];
__device__ float g_hmid[(size_t)NN * HID];
__device__ float g_h1[(size_t)NN * HID];
__device__ int   g_src[EE];
__device__ int   g_dst[EE];
__device__ int   g_col[EE];
__device__ int   g_deg[NN];
__device__ int   g_rowptr[NN + 1];
__device__ int   g_cursor[NN];
__device__ int   g_bsum[256];
__device__ int   g_boff[256];
__device__ int   g_is64;

// ---------------- f32x2 packed-math helpers ----------------------------------
__device__ __forceinline__ unsigned long long pack2(float lo, float hi) {
    unsigned long long r;
    asm("mov.b64 %0, {%1, %2};" : "=l"(r) : "f"(lo), "f"(hi));
    return r;
}
__device__ __forceinline__ unsigned long long fma2(
    unsigned long long a, unsigned long long b, unsigned long long c) {
    unsigned long long d;
    asm("fma.rn.f32x2 %0, %1, %2, %3;" : "=l"(d) : "l"(a), "l"(b), "l"(c));
    return d;
}
__device__ __forceinline__ float2 unpack2(unsigned long long v) {
    float2 f;
    asm("mov.b64 {%0, %1}, %2;" : "=f"(f.x), "=f"(f.y) : "l"(v));
    return f;
}

// ---------------- edge dtype detection ---------------------------------------
__global__ void detect_k(const unsigned int* __restrict__ ei) {
    unsigned v = ei[threadIdx.x * 2 + 1];
    unsigned nz = __ballot_sync(0xFFFFFFFFu, v != 0u);
    if (threadIdx.x == 0) g_is64 = (nz == 0u) ? 1 : 0;
}

__global__ void zero_deg_k() {
    int i = blockIdx.x * blockDim.x + threadIdx.x;
    if (i < NN) g_deg[i] = 0;
}

// decode src/dst + histogram degrees by dst
__global__ void decode_hist_k(const void* __restrict__ ei, int E) {
    int i = blockIdx.x * blockDim.x + threadIdx.x;
    if (i >= E) return;
    int s, d;
    if (g_is64) {
        const long long* p = (const long long*)ei;
        s = (int)p[i];
        d = (int)p[(size_t)E + i];
    } else {
        const int* p = (const int*)ei;
        s = p[i];
        d = p[E + i];
    }
    g_src[i] = s;
    g_dst[i] = d;
    atomicAdd(&g_deg[d], 1);
}

// ---- multi-block exclusive scan of g_deg -> g_rowptr/g_cursor ----------------
__global__ void block_sum_k(int n) {
    __shared__ int sh[8];
    int i = blockIdx.x * 256 + threadIdx.x;
    int lane = threadIdx.x & 31;
    int wid = threadIdx.x >> 5;
    int v = (i < n) ? g_deg[i] : 0;
#pragma unroll
    for (int o = 16; o; o >>= 1) v += __shfl_down_sync(0xFFFFFFFFu, v, o);
    if (lane == 0) sh[wid] = v;
    __syncthreads();
    if (threadIdx.x == 0) {
        int s = 0;
#pragma unroll
        for (int w = 0; w < 8; w++) s += sh[w];
        g_bsum[blockIdx.x] = s;
    }
}

__global__ void scan_bsums_k(int nb) {
    __shared__ int sh[256];
    int tid = threadIdx.x;
    int v = (tid < nb) ? g_bsum[tid] : 0;
    sh[tid] = v;
    __syncthreads();
    for (int off = 1; off < 256; off <<= 1) {
        int t = (tid >= off) ? sh[tid - off] : 0;
        __syncthreads();
        sh[tid] += t;
        __syncthreads();
    }
    g_boff[tid] = sh[tid] - v;   // exclusive
}

__global__ void rowptr_k(int n) {
    __shared__ int sh[256];
    int i = blockIdx.x * 256 + threadIdx.x;
    int tid = threadIdx.x;
    int v = (i < n) ? g_deg[i] : 0;
    sh[tid] = v;
    __syncthreads();
    for (int off = 1; off < 256; off <<= 1) {
        int t = (tid >= off) ? sh[tid - off] : 0;
        __syncthreads();
        sh[tid] += t;
        __syncthreads();
    }
    if (i <= n - 1 || i == n) {}
    int ex = g_boff[blockIdx.x] + sh[tid] - v;
    if (i < n) {
        g_rowptr[i] = ex;
        g_cursor[i] = ex;
        if (i == n - 1) g_rowptr[n] = ex + v;
    }
}

__global__ void fill_k(int E) {
    int i = blockIdx.x * blockDim.x + threadIdx.x;
    if (i >= E) return;
    int d = g_dst[i];
    int pos = atomicAdd(&g_cursor[d], 1);
    g_col[pos] = g_src[i];
}

// ---------------- gather aggregation: warp per node ---------------------------
__global__ __launch_bounds__(256) void gather_k(
    const float4* __restrict__ X, const float* __restrict__ eps,
    float4* __restrict__ out, int M)
{
    int warp = (blockIdx.x * blockDim.x + threadIdx.x) >> 5;
    int lane = threadIdx.x & 31;
    if (warp >= M) return;
    const float alpha = 1.0f + *eps;

    float4 a0 = make_float4(0.f, 0.f, 0.f, 0.f);
    float4 a1 = make_float4(0.f, 0.f, 0.f, 0.f);

    int beg = g_rowptr[warp];
    int end = g_rowptr[warp + 1];
    int e = beg;
    for (; e + 1 < end; e += 2) {
        int s0 = __ldg(&g_col[e]);
        int s1 = __ldg(&g_col[e + 1]);
        float4 v00 = X[(size_t)s0 * 64 + lane];
        float4 v01 = X[(size_t)s0 * 64 + 32 + lane];
        float4 v10 = X[(size_t)s1 * 64 + lane];
        float4 v11 = X[(size_t)s1 * 64 + 32 + lane];
        a0.x += v00.x + v10.x; a0.y += v00.y + v10.y;
        a0.z += v00.z + v10.z; a0.w += v00.w + v10.w;
        a1.x += v01.x + v11.x; a1.y += v01.y + v11.y;
        a1.z += v01.z + v11.z; a1.w += v01.w + v11.w;
    }
    if (e < end) {
        int s0 = __ldg(&g_col[e]);
        float4 v00 = X[(size_t)s0 * 64 + lane];
        float4 v01 = X[(size_t)s0 * 64 + 32 + lane];
        a0.x += v00.x; a0.y += v00.y; a0.z += v00.z; a0.w += v00.w;
        a1.x += v01.x; a1.y += v01.y; a1.z += v01.z; a1.w += v01.w;
    }

    float4 x0 = X[(size_t)warp * 64 + lane];
    float4 x1 = X[(size_t)warp * 64 + 32 + lane];
    a0.x = fmaf(alpha, x0.x, a0.x); a0.y = fmaf(alpha, x0.y, a0.y);
    a0.z = fmaf(alpha, x0.z, a0.z); a0.w = fmaf(alpha, x0.w, a0.w);
    a1.x = fmaf(alpha, x1.x, a1.x); a1.y = fmaf(alpha, x1.y, a1.y);
    a1.z = fmaf(alpha, x1.z, a1.z); a1.w = fmaf(alpha, x1.w, a1.w);
    out[(size_t)warp * 64 + lane] = a0;
    out[(size_t)warp * 64 + 32 + lane] = a1;
}

// ---------------- f32x2 GEMM, K=256 fixed, 128x128 tile ----------------------
#define BM 128
#define BN 128
#define BK 16

template <bool RELU>
__global__ __launch_bounds__(256) void gemm_f32x2(
    const float* __restrict__ A,
    const float* __restrict__ W, const float* __restrict__ bias,
    float* __restrict__ C, int M, int Ncols)
{
    __shared__ float As[2][BK][BM];
    __shared__ float Bs[2][BK][BN];

    const int tid = threadIdx.x;
    const int blockRow = blockIdx.x * BM;
    const int blockCol = blockIdx.y * BN;
    const int tx = tid & 15;   // 16 * 8 cols = 128
    const int ty = tid >> 4;   // 16 * 8 rows = 128

    unsigned long long acc[8][4];
#pragma unroll
    for (int i = 0; i < 8; i++)
#pragma unroll
        for (int j = 0; j < 4; j++) acc[i][j] = 0ull;

    auto loadA = [&](int kt, int buf) {
#pragma unroll
        for (int j = 0; j < 2; j++) {
            int idx = tid * 2 + j;            // 0..511
            int r = idx >> 2;                 // 0..127
            int kc = (idx & 3) * 4;           // 0,4,8,12
            int grow = blockRow + r;
            float4 v = make_float4(0.f, 0.f, 0.f, 0.f);
            if (grow < M)
                v = *(const float4*)(A + (size_t)grow * 256 + kt + kc);
            As[buf][kc + 0][r] = v.x;
            As[buf][kc + 1][r] = v.y;
            As[buf][kc + 2][r] = v.z;
            As[buf][kc + 3][r] = v.w;
        }
    };
    auto loadB = [&](int kt, int buf) {
        int r = tid >> 4;                     // 0..15
        int nc = (tid & 15) * 8;              // 0..120
        const float* wp = W + (size_t)(kt + r) * Ncols + blockCol + nc;
        float4 v0 = *(const float4*)(wp);
        float4 v1 = *(const float4*)(wp + 4);
        *(float4*)&Bs[buf][r][nc] = v0;
        *(float4*)&Bs[buf][r][nc + 4] = v1;
    };

    loadA(0, 0);
    loadB(0, 0);
    __syncthreads();

    for (int kt = 0; kt < 256; kt += BK) {
        int buf = (kt / BK) & 1;
        int nbuf = buf ^ 1;
        if (kt + BK < 256) {
            loadA(kt + BK, nbuf);
            loadB(kt + BK, nbuf);
        }
#pragma unroll
        for (int k = 0; k < BK; k++) {
            const float4* ap = (const float4*)&As[buf][k][ty * 8];
            float4 a0 = ap[0], a1 = ap[1];
            const float4* bp = (const float4*)&Bs[buf][k][tx * 8];
            float4 b0 = bp[0], b1 = bp[1];
            unsigned long long bb[4];
            bb[0] = pack2(b0.x, b0.y);
            bb[1] = pack2(b0.z, b0.w);
            bb[2] = pack2(b1.x, b1.y);
            bb[3] = pack2(b1.z, b1.w);
            float a[8] = {a0.x, a0.y, a0.z, a0.w, a1.x, a1.y, a1.z, a1.w};
#pragma unroll
            for (int i = 0; i < 8; i++) {
                unsigned long long aa = pack2(a[i], a[i]);
#pragma unroll
                for (int j = 0; j < 4; j++)
                    acc[i][j] = fma2(aa, bb[j], acc[i][j]);
            }
        }
        __syncthreads();
    }

    // epilogue
    const float* bp = bias + blockCol + tx * 8;
    float bv[8];
#pragma unroll
    for (int j = 0; j < 8; j++) bv[j] = bp[j];

#pragma unroll
    for (int i = 0; i < 8; i++) {
        int grow = blockRow + ty * 8 + i;
        if (grow >= M) continue;
        float o[8];
#pragma unroll
        for (int j = 0; j < 4; j++) {
            float2 p = unpack2(acc[i][j]);
            o[j * 2 + 0] = p.x + bv[j * 2 + 0];
            o[j * 2 + 1] = p.y + bv[j * 2 + 1];
        }
        if (RELU) {
#pragma unroll
            for (int j = 0; j < 8; j++) o[j] = fmaxf(o[j], 0.f);
        }
        float* cp = C + (size_t)grow * Ncols + blockCol + tx * 8;
        *(float4*)(cp)     = make_float4(o[0], o[1], o[2], o[3]);
        *(float4*)(cp + 4) = make_float4(o[4], o[5], o[6], o[7]);
    }
}

// ---------------- log_softmax over 128-wide rows, warp per row ---------------
__global__ void logsoftmax_k(float* __restrict__ C, int M) {
    int row = blockIdx.x * 8 + (threadIdx.x >> 5);
    int lane = threadIdx.x & 31;
    if (row >= M) return;
    float4 v = *(float4*)(C + (size_t)row * 128 + lane * 4);
    float m = fmaxf(fmaxf(v.x, v.y), fmaxf(v.z, v.w));
#pragma unroll
    for (int o = 16; o; o >>= 1) m = fmaxf(m, __shfl_xor_sync(0xFFFFFFFFu, m, o));
    float s = expf(v.x - m) + expf(v.y - m) + expf(v.z - m) + expf(v.w - m);
#pragma unroll
    for (int o = 16; o; o >>= 1) s += __shfl_xor_sync(0xFFFFFFFFu, s, o);
    float lg = m + logf(s);
    v.x -= lg; v.y -= lg; v.z -= lg; v.w -= lg;
    *(float4*)(C + (size_t)row * 128 + lane * 4) = v;
}

// ---------------- host launch -------------------------------------------------
extern "C" void kernel_launch(void* const* d_in, const int* in_sizes, int n_in,
                              void* d_out, int out_size) {
    const float* x    = (const float*)d_in[0];
    const void*  ei   = d_in[1];
    const float* eps0 = (const float*)d_in[2];
    const float* W1_0 = (const float*)d_in[3];
    const float* b1_0 = (const float*)d_in[4];
    const float* W2_0 = (const float*)d_in[5];
    const float* b2_0 = (const float*)d_in[6];
    const float* eps1 = (const float*)d_in[7];
    const float* W1_1 = (const float*)d_in[8];
    const float* b1_1 = (const float*)d_in[9];
    const float* W2_1 = (const float*)d_in[10];
    const float* b2_1 = (const float*)d_in[11];
    float* out = (float*)d_out;

    int E = in_sizes[1] / 2;
    if (E > EE) E = EE;
    int M = in_sizes[0] / INC;
    if (M > NN) M = NN;

    float* hin  = nullptr;
    float* hmid = nullptr;
    float* h1   = nullptr;
    cudaGetSymbolAddress((void**)&hin,  g_hin);
    cudaGetSymbolAddress((void**)&hmid, g_hmid);
    cudaGetSymbolAddress((void**)&h1,   g_h1);

    const int egrid = (E + 255) / 256;
    const int ngrid = (M + 255) / 256;          // per-node blocks (<=196)
    const int ggrid = (M + 7) / 8;
    const dim3 gemm_grid_h((M + BM - 1) / BM, HID / BN);
    const dim3 gemm_grid_o((M + BM - 1) / BM, OUTC / BN);

    // ---- CSR build ----
    detect_k<<<1, 32>>>((const unsigned int*)ei);
    zero_deg_k<<<ngrid, 256>>>();
    decode_hist_k<<<egrid, 256>>>(ei, E);
    block_sum_k<<<ngrid, 256>>>(M);
    scan_bsums_k<<<1, 256>>>(ngrid);
    rowptr_k<<<ngrid, 256>>>(M);
    fill_k<<<egrid, 256>>>(E);

    // ---- layer 0 ----
    gather_k<<<ggrid, 256>>>((const float4*)x, eps0, (float4*)hin, M);
    gemm_f32x2<true><<<gemm_grid_h, 256>>>(hin, W1_0, b1_0, hmid, M, HID);
    gemm_f32x2<true><<<gemm_grid_h, 256>>>(hmid, W2_0, b2_0, h1, M, HID);

    // ---- layer 1 ----
    gather_k<<<ggrid, 256>>>((const float4*)h1, eps1, (float4*)hin, M);
    gemm_f32x2<true><<<gemm_grid_h, 256>>>(hin, W1_1, b1_1, hmid, M, HID);
    gemm_f32x2<false><<<gemm_grid_o, 256>>>(hmid, W2_1, b2_1, out, M, OUTC);

    // ---- log_softmax ----
    logsoftmax_k<<<(M + 7) / 8, 256>>>(out, M);
}

// round 7
// speedup vs baseline: 3.1597x; 1.5411x over previous
#include <cuda_runtime.h>
#include <cuda_bf16.h>
#include <math.h>
#include <stdint.h>

#define NN 50000
#define EE 800000
#define INC 256
#define HID 256
#define OUTC 128

// ---------------- scratch (static device globals; no allocation) -------------
__device__ float g_hin[(size_t)NN * HID];
__device__ float g_hmid[(size_t)NN * HID];
__device__ float g_h1[(size_t)NN * HID];
__device__ int   g_src[EE];
__device__ int   g_dst[EE];
__device__ int   g_col[EE];
__device__ int   g_deg[NN];
__device__ int   g_rowptr[NN + 1];
__device__ int   g_cursor[NN];
__device__ int   g_bsum[256];
__device__ int   g_boff[256];
__device__ int   g_is64;
// transposed + hi/lo split weights: Wt[n][k] bf16
__device__ __nv_bfloat16 g_wt_hi[4][256 * 256];
__device__ __nv_bfloat16 g_wt_lo[4][256 * 256];

// ---------------- helpers -----------------------------------------------------
__device__ __forceinline__ uint32_t smem_u32(const void* p) {
    uint32_t a;
    asm("{ .reg .u64 t; cvta.to.shared.u64 t, %1; cvt.u32.u64 %0, t; }" : "=r"(a) : "l"(p));
    return a;
}
__device__ __forceinline__ void ldsm_x4(uint32_t* r, uint32_t addr) {
    asm volatile("ldmatrix.sync.aligned.m8n8.x4.shared.b16 {%0,%1,%2,%3}, [%4];"
                 : "=r"(r[0]), "=r"(r[1]), "=r"(r[2]), "=r"(r[3]) : "r"(addr));
}
__device__ __forceinline__ void mma_bf16(float* d, const uint32_t* a, const uint32_t* b) {
    asm volatile(
        "mma.sync.aligned.m16n8k16.row.col.f32.bf16.bf16.f32 "
        "{%0,%1,%2,%3}, {%4,%5,%6,%7}, {%8,%9}, {%0,%1,%2,%3};"
        : "+f"(d[0]), "+f"(d[1]), "+f"(d[2]), "+f"(d[3])
        : "r"(a[0]), "r"(a[1]), "r"(a[2]), "r"(a[3]), "r"(b[0]), "r"(b[1]));
}

// ---------------- edge dtype detection ---------------------------------------
__global__ void detect_k(const unsigned int* __restrict__ ei) {
    unsigned v = ei[threadIdx.x * 2 + 1];
    unsigned nz = __ballot_sync(0xFFFFFFFFu, v != 0u);
    if (threadIdx.x == 0) g_is64 = (nz == 0u) ? 1 : 0;
}

__global__ void zero_deg_k() {
    int i = blockIdx.x * blockDim.x + threadIdx.x;
    if (i < NN) g_deg[i] = 0;
}

__global__ void decode_hist_k(const void* __restrict__ ei, int E) {
    int i = blockIdx.x * blockDim.x + threadIdx.x;
    if (i >= E) return;
    int s, d;
    if (g_is64) {
        const long long* p = (const long long*)ei;
        s = (int)p[i];
        d = (int)p[(size_t)E + i];
    } else {
        const int* p = (const int*)ei;
        s = p[i];
        d = p[E + i];
    }
    g_src[i] = s;
    g_dst[i] = d;
    atomicAdd(&g_deg[d], 1);
}

__global__ void block_sum_k(int n) {
    __shared__ int sh[8];
    int i = blockIdx.x * 256 + threadIdx.x;
    int lane = threadIdx.x & 31;
    int wid = threadIdx.x >> 5;
    int v = (i < n) ? g_deg[i] : 0;
#pragma unroll
    for (int o = 16; o; o >>= 1) v += __shfl_down_sync(0xFFFFFFFFu, v, o);
    if (lane == 0) sh[wid] = v;
    __syncthreads();
    if (threadIdx.x == 0) {
        int s = 0;
#pragma unroll
        for (int w = 0; w < 8; w++) s += sh[w];
        g_bsum[blockIdx.x] = s;
    }
}

__global__ void scan_bsums_k(int nb) {
    __shared__ int sh[256];
    int tid = threadIdx.x;
    int v = (tid < nb) ? g_bsum[tid] : 0;
    sh[tid] = v;
    __syncthreads();
    for (int off = 1; off < 256; off <<= 1) {
        int t = (tid >= off) ? sh[tid - off] : 0;
        __syncthreads();
        sh[tid] += t;
        __syncthreads();
    }
    g_boff[tid] = sh[tid] - v;
}

__global__ void rowptr_k(int n) {
    __shared__ int sh[256];
    int i = blockIdx.x * 256 + threadIdx.x;
    int tid = threadIdx.x;
    int v = (i < n) ? g_deg[i] : 0;
    sh[tid] = v;
    __syncthreads();
    for (int off = 1; off < 256; off <<= 1) {
        int t = (tid >= off) ? sh[tid - off] : 0;
        __syncthreads();
        sh[tid] += t;
        __syncthreads();
    }
    int ex = g_boff[blockIdx.x] + sh[tid] - v;
    if (i < n) {
        g_rowptr[i] = ex;
        g_cursor[i] = ex;
        if (i == n - 1) g_rowptr[n] = ex + v;
    }
}

__global__ void fill_k(int E) {
    int i = blockIdx.x * blockDim.x + threadIdx.x;
    if (i >= E) return;
    int d = g_dst[i];
    int pos = atomicAdd(&g_cursor[d], 1);
    g_col[pos] = g_src[i];
}

// ---------------- weight transpose + hi/lo split ------------------------------
__global__ void tw_k(const float* __restrict__ W, int Ncols,
                     __nv_bfloat16* __restrict__ Hi, __nv_bfloat16* __restrict__ Lo) {
    int id = blockIdx.x * 256 + threadIdx.x;
    if (id >= 256 * Ncols) return;
    int k = id / Ncols, n = id % Ncols;
    float w = W[id];
    __nv_bfloat16 h = __float2bfloat16_rn(w);
    float r = w - __bfloat162float(h);
    __nv_bfloat16 l = __float2bfloat16_rn(r);
    Hi[(size_t)n * 256 + k] = h;
    Lo[(size_t)n * 256 + k] = l;
}

// ---------------- gather aggregation: warp per node ---------------------------
__global__ __launch_bounds__(256) void gather_k(
    const float4* __restrict__ X, const float* __restrict__ eps,
    float4* __restrict__ out, int M)
{
    int warp = (blockIdx.x * blockDim.x + threadIdx.x) >> 5;
    int lane = threadIdx.x & 31;
    if (warp >= M) return;
    const float alpha = 1.0f + *eps;

    float4 a0 = make_float4(0.f, 0.f, 0.f, 0.f);
    float4 a1 = make_float4(0.f, 0.f, 0.f, 0.f);

    int beg = g_rowptr[warp];
    int end = g_rowptr[warp + 1];
    int e = beg;
    for (; e + 1 < end; e += 2) {
        int s0 = __ldg(&g_col[e]);
        int s1 = __ldg(&g_col[e + 1]);
        float4 v00 = X[(size_t)s0 * 64 + lane];
        float4 v01 = X[(size_t)s0 * 64 + 32 + lane];
        float4 v10 = X[(size_t)s1 * 64 + lane];
        float4 v11 = X[(size_t)s1 * 64 + 32 + lane];
        a0.x += v00.x + v10.x; a0.y += v00.y + v10.y;
        a0.z += v00.z + v10.z; a0.w += v00.w + v10.w;
        a1.x += v01.x + v11.x; a1.y += v01.y + v11.y;
        a1.z += v01.z + v11.z; a1.w += v01.w + v11.w;
    }
    if (e < end) {
        int s0 = __ldg(&g_col[e]);
        float4 v00 = X[(size_t)s0 * 64 + lane];
        float4 v01 = X[(size_t)s0 * 64 + 32 + lane];
        a0.x += v00.x; a0.y += v00.y; a0.z += v00.z; a0.w += v00.w;
        a1.x += v01.x; a1.y += v01.y; a1.z += v01.z; a1.w += v01.w;
    }

    float4 x0 = X[(size_t)warp * 64 + lane];
    float4 x1 = X[(size_t)warp * 64 + 32 + lane];
    a0.x = fmaf(alpha, x0.x, a0.x); a0.y = fmaf(alpha, x0.y, a0.y);
    a0.z = fmaf(alpha, x0.z, a0.z); a0.w = fmaf(alpha, x0.w, a0.w);
    a1.x = fmaf(alpha, x1.x, a1.x); a1.y = fmaf(alpha, x1.y, a1.y);
    a1.z = fmaf(alpha, x1.z, a1.z); a1.w = fmaf(alpha, x1.w, a1.w);
    out[(size_t)warp * 64 + lane] = a0;
    out[(size_t)warp * 64 + 32 + lane] = a1;
}

// ---------------- mma.sync bf16 hi/lo GEMM ------------------------------------
// C[M,Ncols] = act(A[M,256] @ W[256,Ncols] + bias). CTA tile 128x128, K=256.
// B = Wt[n][k] hi/lo, whole 128x256 slice resident in smem (528B padded rows).
// A fp32 -> bf16 hi/lo converted per 32-wide K chunk into 80B padded rows.
// 8 warps as 4(m) x 2(n): warp tile 32 x 64. 3 passes: hi*hi + hi*lo + lo*hi.
#define BSTR 528
#define ASTR 80
#define SM_BHI 0
#define SM_BLO (128 * BSTR)
#define SM_AHI (2 * 128 * BSTR)
#define SM_ALO (SM_AHI + 128 * ASTR)
#define SM_TOTAL (SM_ALO + 128 * ASTR)

__global__ void __launch_bounds__(256, 1) gemm_mma(
    const float* __restrict__ A,
    const __nv_bfloat16* __restrict__ Whi, const __nv_bfloat16* __restrict__ Wlo,
    const float* __restrict__ bias,
    float* __restrict__ C, int M, int Ncols, int relu)
{
    extern __shared__ char smem[];
    const uint32_t sb = smem_u32(smem);
    const int tid = threadIdx.x;
    const int wid = tid >> 5, lane = tid & 31;
    const int blockRow = blockIdx.x * 128;
    const int cb = blockIdx.y;
    const int warp_m = wid & 3, warp_n = wid >> 2;

    // ---- load B hi/lo (128 n-rows x 256 k) into padded smem ----
    {
        const uint4* sh = (const uint4*)(Whi + (size_t)cb * 128 * 256);
        const uint4* sl = (const uint4*)(Wlo + (size_t)cb * 128 * 256);
        for (int f = tid; f < 4096; f += 256) {
            int n = f >> 5, kc = f & 31;        // 32 uint4 per 256-elem row
            uint4 vh = sh[n * 32 + kc];
            uint4 vl = sl[n * 32 + kc];
            *(uint4*)(smem + SM_BHI + n * BSTR + kc * 16) = vh;
            *(uint4*)(smem + SM_BLO + n * BSTR + kc * 16) = vl;
        }
    }

    float acc[2][8][4];
#pragma unroll
    for (int mf = 0; mf < 2; mf++)
#pragma unroll
        for (int nf = 0; nf < 8; nf++)
#pragma unroll
            for (int q = 0; q < 4; q++) acc[mf][nf][q] = 0.f;

    float4 pf[4];
    auto loadA = [&](int c) {
#pragma unroll
        for (int j = 0; j < 4; j++) {
            int f = j * 256 + tid;
            int row = f >> 3, kc = (f & 7) * 4;
            int grow = blockRow + row;
            pf[j] = (grow < M) ? *(const float4*)(A + (size_t)grow * 256 + c * 32 + kc)
                               : make_float4(0.f, 0.f, 0.f, 0.f);
        }
    };
    loadA(0);

    for (int c = 0; c < 8; c++) {
        // convert prefetched A chunk -> smem hi/lo
#pragma unroll
        for (int j = 0; j < 4; j++) {
            int f = j * 256 + tid;
            int row = f >> 3, kc = (f & 7) * 4;
            float xs[4] = {pf[j].x, pf[j].y, pf[j].z, pf[j].w};
            unsigned short h[4], l[4];
#pragma unroll
            for (int q = 0; q < 4; q++) {
                __nv_bfloat16 bh = __float2bfloat16_rn(xs[q]);
                float r = xs[q] - __bfloat162float(bh);
                __nv_bfloat16 bl = __float2bfloat16_rn(r);
                h[q] = __bfloat16_as_ushort(bh);
                l[q] = __bfloat16_as_ushort(bl);
            }
            uint2 vh = make_uint2((uint32_t)h[0] | ((uint32_t)h[1] << 16),
                                  (uint32_t)h[2] | ((uint32_t)h[3] << 16));
            uint2 vl = make_uint2((uint32_t)l[0] | ((uint32_t)l[1] << 16),
                                  (uint32_t)l[2] | ((uint32_t)l[3] << 16));
            *(uint2*)(smem + SM_AHI + row * ASTR + kc * 2) = vh;
            *(uint2*)(smem + SM_ALO + row * ASTR + kc * 2) = vl;
        }
        __syncthreads();
        if (c < 7) loadA(c + 1);

#pragma unroll
        for (int s = 0; s < 2; s++) {
            const int k0 = s * 16;                 // k within the 32-wide A chunk
            const int bk0 = c * 32 + k0;           // k within the full 256-wide B rows
            uint32_t ah[2][4], al[2][4];
#pragma unroll
            for (int mf = 0; mf < 2; mf++) {
                int row = warp_m * 32 + mf * 16 + (lane & 15);
                uint32_t addr = sb + SM_AHI + row * ASTR + (k0 + (lane >> 4) * 8) * 2;
                ldsm_x4(ah[mf], addr);
                ldsm_x4(al[mf], addr + (SM_ALO - SM_AHI));
            }
            uint32_t bh[8][2], bl[8][2];
#pragma unroll
            for (int q = 0; q < 4; q++) {
                int trow = lane & 7;
                int tsel = lane >> 3;
                int n = warp_n * 64 + q * 16 + trow + ((tsel >> 1) * 8);
                int koff = (tsel & 1) * 8;
                uint32_t addr = sb + SM_BHI + n * BSTR + (bk0 + koff) * 2;
                uint32_t t[4];
                ldsm_x4(t, addr);
                bh[q * 2][0] = t[0]; bh[q * 2][1] = t[1];
                bh[q * 2 + 1][0] = t[2]; bh[q * 2 + 1][1] = t[3];
                ldsm_x4(t, addr + (SM_BLO - SM_BHI));
                bl[q * 2][0] = t[0]; bl[q * 2][1] = t[1];
                bl[q * 2 + 1][0] = t[2]; bl[q * 2 + 1][1] = t[3];
            }
#pragma unroll
            for (int mf = 0; mf < 2; mf++)
#pragma unroll
                for (int nf = 0; nf < 8; nf++) {
                    mma_bf16(acc[mf][nf], ah[mf], bh[nf]);
                    mma_bf16(acc[mf][nf], ah[mf], bl[nf]);
                    mma_bf16(acc[mf][nf], al[mf], bh[nf]);
                }
        }
        __syncthreads();
    }

    // ---- epilogue ----
    const int colbase = cb * 128 + warp_n * 64;
#pragma unroll
    for (int mf = 0; mf < 2; mf++) {
        int r0 = blockRow + warp_m * 32 + mf * 16 + (lane >> 2);
        int r1 = r0 + 8;
#pragma unroll
        for (int nf = 0; nf < 8; nf++) {
            int col = colbase + nf * 8 + (lane & 3) * 2;
            float b0 = bias[col], b1 = bias[col + 1];
            float o0 = acc[mf][nf][0] + b0, o1 = acc[mf][nf][1] + b1;
            float o2 = acc[mf][nf][2] + b0, o3 = acc[mf][nf][3] + b1;
            if (relu) {
                o0 = fmaxf(o0, 0.f); o1 = fmaxf(o1, 0.f);
                o2 = fmaxf(o2, 0.f); o3 = fmaxf(o3, 0.f);
            }
            if (r0 < M) *(float2*)(C + (size_t)r0 * Ncols + col) = make_float2(o0, o1);
            if (r1 < M) *(float2*)(C + (size_t)r1 * Ncols + col) = make_float2(o2, o3);
        }
    }
}

// ---------------- log_softmax over 128-wide rows, warp per row ---------------
__global__ void logsoftmax_k(float* __restrict__ C, int M) {
    int row = blockIdx.x * 8 + (threadIdx.x >> 5);
    int lane = threadIdx.x & 31;
    if (row >= M) return;
    float4 v = *(float4*)(C + (size_t)row * 128 + lane * 4);
    float m = fmaxf(fmaxf(v.x, v.y), fmaxf(v.z, v.w));
#pragma unroll
    for (int o = 16; o; o >>= 1) m = fmaxf(m, __shfl_xor_sync(0xFFFFFFFFu, m, o));
    float s = expf(v.x - m) + expf(v.y - m) + expf(v.z - m) + expf(v.w - m);
#pragma unroll
    for (int o = 16; o; o >>= 1) s += __shfl_xor_sync(0xFFFFFFFFu, s, o);
    float lg = m + logf(s);
    v.x -= lg; v.y -= lg; v.z -= lg; v.w -= lg;
    *(float4*)(C + (size_t)row * 128 + lane * 4) = v;
}

// ---------------- host launch -------------------------------------------------
extern "C" void kernel_launch(void* const* d_in, const int* in_sizes, int n_in,
                              void* d_out, int out_size) {
    const float* x    = (const float*)d_in[0];
    const void*  ei   = d_in[1];
    const float* eps0 = (const float*)d_in[2];
    const float* W1_0 = (const float*)d_in[3];
    const float* b1_0 = (const float*)d_in[4];
    const float* W2_0 = (const float*)d_in[5];
    const float* b2_0 = (const float*)d_in[6];
    const float* eps1 = (const float*)d_in[7];
    const float* W1_1 = (const float*)d_in[8];
    const float* b1_1 = (const float*)d_in[9];
    const float* W2_1 = (const float*)d_in[10];
    const float* b2_1 = (const float*)d_in[11];
    float* out = (float*)d_out;

    int E = in_sizes[1] / 2;
    if (E > EE) E = EE;
    int M = in_sizes[0] / INC;
    if (M > NN) M = NN;

    float* hin  = nullptr;
    float* hmid = nullptr;
    float* h1   = nullptr;
    __nv_bfloat16* whi = nullptr;
    __nv_bfloat16* wlo = nullptr;
    cudaGetSymbolAddress((void**)&hin,  g_hin);
    cudaGetSymbolAddress((void**)&hmid, g_hmid);
    cudaGetSymbolAddress((void**)&h1,   g_h1);
    cudaGetSymbolAddress((void**)&whi,  g_wt_hi);
    cudaGetSymbolAddress((void**)&wlo,  g_wt_lo);

    cudaFuncSetAttribute(gemm_mma, cudaFuncAttributeMaxDynamicSharedMemorySize, SM_TOTAL);

    const int egrid = (E + 255) / 256;
    const int ngrid = (M + 255) / 256;
    const int ggrid = (M + 7) / 8;
    const int mtiles = (M + 127) / 128;
    const dim3 grid_h(mtiles, 2);
    const dim3 grid_o(mtiles, 1);
    const int WSZ = 256 * 256;

    // ---- CSR build ----
    detect_k<<<1, 32>>>((const unsigned int*)ei);
    zero_deg_k<<<ngrid, 256>>>();
    decode_hist_k<<<egrid, 256>>>(ei, E);
    block_sum_k<<<ngrid, 256>>>(M);
    scan_bsums_k<<<1, 256>>>(ngrid);
    rowptr_k<<<ngrid, 256>>>(M);
    fill_k<<<egrid, 256>>>(E);

    // ---- weight transpose + split ----
    tw_k<<<(256 * HID + 255) / 256, 256>>>(W1_0, HID, whi + 0 * WSZ, wlo + 0 * WSZ);
    tw_k<<<(256 * HID + 255) / 256, 256>>>(W2_0, HID, whi + 1 * WSZ, wlo + 1 * WSZ);
    tw_k<<<(256 * HID + 255) / 256, 256>>>(W1_1, HID, whi + 2 * WSZ, wlo + 2 * WSZ);
    tw_k<<<(256 * OUTC + 255) / 256, 256>>>(W2_1, OUTC, whi + 3 * WSZ, wlo + 3 * WSZ);

    // ---- layer 0 ----
    gather_k<<<ggrid, 256>>>((const float4*)x, eps0, (float4*)hin, M);
    gemm_mma<<<grid_h, 256, SM_TOTAL>>>(hin, whi + 0 * WSZ, wlo + 0 * WSZ, b1_0, hmid, M, HID, 1);
    gemm_mma<<<grid_h, 256, SM_TOTAL>>>(hmid, whi + 1 * WSZ, wlo + 1 * WSZ, b2_0, h1, M, HID, 1);

    // ---- layer 1 ----
    gather_k<<<ggrid, 256>>>((const float4*)h1, eps1, (float4*)hin, M);
    gemm_mma<<<grid_h, 256, SM_TOTAL>>>(hin, whi + 2 * WSZ, wlo + 2 * WSZ, b1_1, hmid, M, HID, 1);
    gemm_mma<<<grid_o, 256, SM_TOTAL>>>(hmid, whi + 3 * WSZ, wlo + 3 * WSZ, b2_1, out, M, OUTC, 0);

    // ---- log_softmax ----
    logsoftmax_k<<<(M + 7) / 8, 256>>>(out, M);
}

// round 9
// speedup vs baseline: 3.4580x; 1.0944x over previous
#include <cuda_runtime.h>
#include <cuda_bf16.h>
#include <math.h>
#include <stdint.h>

#define NN 50000
#define EE 800000
#define INC 256
#define HID 256
#define OUTC 128

// ---------------- scratch (static device globals; no allocation) -------------
__device__ __nv_bfloat16 g_xhi[(size_t)NN * HID];  // split of gather output
__device__ __nv_bfloat16 g_xlo[(size_t)NN * HID];
__device__ __nv_bfloat16 g_mhi[(size_t)NN * HID];  // split of MLP hidden
__device__ __nv_bfloat16 g_mlo[(size_t)NN * HID];
__device__ float g_h1[(size_t)NN * HID];           // layer-0 output (fp32)
__device__ int   g_src[EE];
__device__ int   g_dst[EE];
__device__ int   g_col[EE];
__device__ int   g_deg[NN];
__device__ int   g_rowptr[NN + 1];
__device__ int   g_cursor[NN];
__device__ int   g_bsum[256];
__device__ int   g_boff[256];
__device__ int   g_is64;
// transposed + hi/lo split weights: Wt[n][k] bf16
__device__ __nv_bfloat16 g_wt_hi[4][256 * 256];
__device__ __nv_bfloat16 g_wt_lo[4][256 * 256];

// ---------------- helpers -----------------------------------------------------
__device__ __forceinline__ uint32_t smem_u32(const void* p) {
    uint32_t a;
    asm("{ .reg .u64 t; cvta.to.shared.u64 t, %1; cvt.u32.u64 %0, t; }" : "=r"(a) : "l"(p));
    return a;
}
__device__ __forceinline__ void ldsm_x4(uint32_t* r, uint32_t addr) {
    asm volatile("ldmatrix.sync.aligned.m8n8.x4.shared.b16 {%0,%1,%2,%3}, [%4];"
                 : "=r"(r[0]), "=r"(r[1]), "=r"(r[2]), "=r"(r[3]) : "r"(addr));
}
__device__ __forceinline__ void mma_bf16(float* d, const uint32_t* a, const uint32_t* b) {
    asm volatile(
        "mma.sync.aligned.m16n8k16.row.col.f32.bf16.bf16.f32 "
        "{%0,%1,%2,%3}, {%4,%5,%6,%7}, {%8,%9}, {%0,%1,%2,%3};"
        : "+f"(d[0]), "+f"(d[1]), "+f"(d[2]), "+f"(d[3])
        : "r"(a[0]), "r"(a[1]), "r"(a[2]), "r"(a[3]), "r"(b[0]), "r"(b[1]));
}
// split fp32 -> (hi, lo) bf16 pair
__device__ __forceinline__ void split1(float v, unsigned short& h, unsigned short& l) {
    __nv_bfloat16 bh = __float2bfloat16_rn(v);
    float r = v - __bfloat162float(bh);
    __nv_bfloat16 bl = __float2bfloat16_rn(r);
    h = __bfloat16_as_ushort(bh);
    l = __bfloat16_as_ushort(bl);
}
__device__ __forceinline__ void split4(float4 v, uint2& hh, uint2& ll) {
    unsigned short h[4], l[4];
    split1(v.x, h[0], l[0]); split1(v.y, h[1], l[1]);
    split1(v.z, h[2], l[2]); split1(v.w, h[3], l[3]);
    hh = make_uint2((uint32_t)h[0] | ((uint32_t)h[1] << 16),
                    (uint32_t)h[2] | ((uint32_t)h[3] << 16));
    ll = make_uint2((uint32_t)l[0] | ((uint32_t)l[1] << 16),
                    (uint32_t)l[2] | ((uint32_t)l[3] << 16));
}

// ---------------- edge dtype detection ---------------------------------------
__global__ void detect_k(const unsigned int* __restrict__ ei) {
    unsigned v = ei[threadIdx.x * 2 + 1];
    unsigned nz = __ballot_sync(0xFFFFFFFFu, v != 0u);
    if (threadIdx.x == 0) g_is64 = (nz == 0u) ? 1 : 0;
}

__global__ void zero_deg_k() {
    int i = blockIdx.x * blockDim.x + threadIdx.x;
    if (i < NN) g_deg[i] = 0;
}

__global__ void decode_hist_k(const void* __restrict__ ei, int E) {
    int i = blockIdx.x * blockDim.x + threadIdx.x;
    if (i >= E) return;
    int s, d;
    if (g_is64) {
        const long long* p = (const long long*)ei;
        s = (int)p[i];
        d = (int)p[(size_t)E + i];
    } else {
        const int* p = (const int*)ei;
        s = p[i];
        d = p[E + i];
    }
    g_src[i] = s;
    g_dst[i] = d;
    atomicAdd(&g_deg[d], 1);
}

__global__ void block_sum_k(int n) {
    __shared__ int sh[8];
    int i = blockIdx.x * 256 + threadIdx.x;
    int lane = threadIdx.x & 31;
    int wid = threadIdx.x >> 5;
    int v = (i < n) ? g_deg[i] : 0;
#pragma unroll
    for (int o = 16; o; o >>= 1) v += __shfl_down_sync(0xFFFFFFFFu, v, o);
    if (lane == 0) sh[wid] = v;
    __syncthreads();
    if (threadIdx.x == 0) {
        int s = 0;
#pragma unroll
        for (int w = 0; w < 8; w++) s += sh[w];
        g_bsum[blockIdx.x] = s;
    }
}

__global__ void scan_bsums_k(int nb) {
    __shared__ int sh[256];
    int tid = threadIdx.x;
    int v = (tid < nb) ? g_bsum[tid] : 0;
    sh[tid] = v;
    __syncthreads();
    for (int off = 1; off < 256; off <<= 1) {
        int t = (tid >= off) ? sh[tid - off] : 0;
        __syncthreads();
        sh[tid] += t;
        __syncthreads();
    }
    g_boff[tid] = sh[tid] - v;
}

__global__ void rowptr_k(int n) {
    __shared__ int sh[256];
    int i = blockIdx.x * 256 + threadIdx.x;
    int tid = threadIdx.x;
    int v = (i < n) ? g_deg[i] : 0;
    sh[tid] = v;
    __syncthreads();
    for (int off = 1; off < 256; off <<= 1) {
        int t = (tid >= off) ? sh[tid - off] : 0;
        __syncthreads();
        sh[tid] += t;
        __syncthreads();
    }
    int ex = g_boff[blockIdx.x] + sh[tid] - v;
    if (i < n) {
        g_rowptr[i] = ex;
        g_cursor[i] = ex;
        if (i == n - 1) g_rowptr[n] = ex + v;
    }
}

__global__ void fill_k(int E) {
    int i = blockIdx.x * blockDim.x + threadIdx.x;
    if (i >= E) return;
    int d = g_dst[i];
    int pos = atomicAdd(&g_cursor[d], 1);
    g_col[pos] = g_src[i];
}

// ---------------- weight transpose + hi/lo split ------------------------------
__global__ void tw_k(const float* __restrict__ W, int Ncols,
                     __nv_bfloat16* __restrict__ Hi, __nv_bfloat16* __restrict__ Lo) {
    int id = blockIdx.x * 256 + threadIdx.x;
    if (id >= 256 * Ncols) return;
    int k = id / Ncols, n = id % Ncols;
    float w = W[id];
    unsigned short h, l;
    split1(w, h, l);
    Hi[(size_t)n * 256 + k] = __ushort_as_bfloat16(h);
    Lo[(size_t)n * 256 + k] = __ushort_as_bfloat16(l);
}

// ---------------- gather aggregation: warp per node, split bf16 output --------
__global__ __launch_bounds__(256) void gather_k(
    const float4* __restrict__ X, const float* __restrict__ eps,
    __nv_bfloat16* __restrict__ Ohi, __nv_bfloat16* __restrict__ Olo, int M)
{
    int warp = (blockIdx.x * blockDim.x + threadIdx.x) >> 5;
    int lane = threadIdx.x & 31;
    if (warp >= M) return;
    const float alpha = 1.0f + *eps;

    float4 a0 = make_float4(0.f, 0.f, 0.f, 0.f);
    float4 a1 = make_float4(0.f, 0.f, 0.f, 0.f);

    int beg = g_rowptr[warp];
    int end = g_rowptr[warp + 1];
    int e = beg;
    for (; e + 1 < end; e += 2) {
        int s0 = __ldg(&g_col[e]);
        int s1 = __ldg(&g_col[e + 1]);
        float4 v00 = X[(size_t)s0 * 64 + lane];
        float4 v01 = X[(size_t)s0 * 64 + 32 + lane];
        float4 v10 = X[(size_t)s1 * 64 + lane];
        float4 v11 = X[(size_t)s1 * 64 + 32 + lane];
        a0.x += v00.x + v10.x; a0.y += v00.y + v10.y;
        a0.z += v00.z + v10.z; a0.w += v00.w + v10.w;
        a1.x += v01.x + v11.x; a1.y += v01.y + v11.y;
        a1.z += v01.z + v11.z; a1.w += v01.w + v11.w;
    }
    if (e < end) {
        int s0 = __ldg(&g_col[e]);
        float4 v00 = X[(size_t)s0 * 64 + lane];
        float4 v01 = X[(size_t)s0 * 64 + 32 + lane];
        a0.x += v00.x; a0.y += v00.y; a0.z += v00.z; a0.w += v00.w;
        a1.x += v01.x; a1.y += v01.y; a1.z += v01.z; a1.w += v01.w;
    }

    float4 x0 = X[(size_t)warp * 64 + lane];
    float4 x1 = X[(size_t)warp * 64 + 32 + lane];
    a0.x = fmaf(alpha, x0.x, a0.x); a0.y = fmaf(alpha, x0.y, a0.y);
    a0.z = fmaf(alpha, x0.z, a0.z); a0.w = fmaf(alpha, x0.w, a0.w);
    a1.x = fmaf(alpha, x1.x, a1.x); a1.y = fmaf(alpha, x1.y, a1.y);
    a1.z = fmaf(alpha, x1.z, a1.z); a1.w = fmaf(alpha, x1.w, a1.w);

    uint2 h0, l0, h1v, l1v;
    split4(a0, h0, l0);
    split4(a1, h1v, l1v);
    size_t base = (size_t)warp * 256 + 4 * lane;
    *(uint2*)(Ohi + base)       = h0;
    *(uint2*)(Olo + base)       = l0;
    *(uint2*)(Ohi + base + 128) = h1v;
    *(uint2*)(Olo + base + 128) = l1v;
}

// ---------------- mma.sync bf16 hi/lo GEMM (pre-split A, cp.async pipeline) ---
// C = act(A @ W + bias), A given as Ahi/Alo bf16 [M][256], W as Wt[n][k] hi/lo.
// CTA tile 128x128, K=256 in 8 chunks of 32. 3-stage cp.async ring for A.
// 8 warps as 4(m) x 2(n). 3 passes: hi*hi + hi*lo + lo*hi.
#define BSTR 528
#define ASTR 80
#define ASTAGE (2 * 128 * ASTR)           // hi + lo per stage = 20480
#define SM_BHI 0
#define SM_BLO (128 * BSTR)
#define SM_A   (2 * 128 * BSTR)
#define SM_TOTAL (SM_A + 3 * ASTAGE)      // 135168 + 61440 = 196608

template <int RELU, int SPLIT>
__global__ void __launch_bounds__(256, 1) gemm_mma(
    const __nv_bfloat16* __restrict__ Ahi, const __nv_bfloat16* __restrict__ Alo,
    const __nv_bfloat16* __restrict__ Whi, const __nv_bfloat16* __restrict__ Wlo,
    const float* __restrict__ bias,
    float* __restrict__ C,
    __nv_bfloat16* __restrict__ Chi, __nv_bfloat16* __restrict__ Clo,
    int M, int Ncols)
{
    extern __shared__ char smem[];
    const uint32_t sb = smem_u32(smem);
    const int tid = threadIdx.x;
    const int wid = tid >> 5, lane = tid & 31;
    const int blockRow = blockIdx.x * 128;
    const int cb = blockIdx.y;
    const int warp_m = wid & 3, warp_n = wid >> 2;

    // ---- load B hi/lo (128 n-rows x 256 k) into padded smem ----
    {
        const uint4* sh = (const uint4*)(Whi + (size_t)cb * 128 * 256);
        const uint4* sl = (const uint4*)(Wlo + (size_t)cb * 128 * 256);
        for (int f = tid; f < 4096; f += 256) {
            int n = f >> 5, kc = f & 31;
            *(uint4*)(smem + SM_BHI + n * BSTR + kc * 16) = sh[n * 32 + kc];
            *(uint4*)(smem + SM_BLO + n * BSTR + kc * 16) = sl[n * 32 + kc];
        }
    }

    // A stage loader: chunk c (32 k-cols) -> stage st
    auto loadA = [&](int c, int st) {
        uint32_t base = sb + SM_A + st * ASTAGE;
#pragma unroll
        for (int j = 0; j < 2; j++) {
            int f = j * 256 + tid;            // 0..511
            int row = f >> 2;                 // 0..127
            int seg = f & 3;                  // 16B (8 bf16) segment
            int grow = blockRow + row;
            int ok = (grow < M);
            size_t off = (size_t)(ok ? grow : 0) * 256 + c * 32 + seg * 8;
            uint32_t dh = base + row * ASTR + seg * 16;
            uint32_t dl = dh + 128 * ASTR;
            int ss = ok ? 16 : 0;
            asm volatile("cp.async.ca.shared.global [%0], [%1], 16, %2;"
                         :: "r"(dh), "l"((const char*)(Ahi + off)), "r"(ss));
            asm volatile("cp.async.ca.shared.global [%0], [%1], 16, %2;"
                         :: "r"(dl), "l"((const char*)(Alo + off)), "r"(ss));
        }
        asm volatile("cp.async.commit_group;");
    };

    float acc[2][8][4];
#pragma unroll
    for (int mf = 0; mf < 2; mf++)
#pragma unroll
        for (int nf = 0; nf < 8; nf++)
#pragma unroll
            for (int q = 0; q < 4; q++) acc[mf][nf][q] = 0.f;

    loadA(0, 0);
    loadA(1, 1);

#pragma unroll
    for (int c = 0; c < 8; c++) {
        if (c + 1 < 8) {
            asm volatile("cp.async.wait_group 1;" ::: "memory");
        } else {
            asm volatile("cp.async.wait_group 0;" ::: "memory");
        }
        __syncthreads();

        const uint32_t abase = sb + SM_A + (c % 3) * ASTAGE;
#pragma unroll
        for (int s = 0; s < 2; s++) {
            const int k0 = s * 16;                 // k within the 32-wide A chunk
            const int bk0 = c * 32 + k0;           // k within full 256-wide B rows
            uint32_t ah[2][4], al[2][4];
#pragma unroll
            for (int mf = 0; mf < 2; mf++) {
                int row = warp_m * 32 + mf * 16 + (lane & 15);
                uint32_t addr = abase + row * ASTR + (k0 + (lane >> 4) * 8) * 2;
                ldsm_x4(ah[mf], addr);
                ldsm_x4(al[mf], addr + 128 * ASTR);
            }
            uint32_t bh[8][2], bl[8][2];
#pragma unroll
            for (int q = 0; q < 4; q++) {
                int trow = lane & 7;
                int tsel = lane >> 3;
                int n = warp_n * 64 + q * 16 + trow + ((tsel >> 1) * 8);
                int koff = (tsel & 1) * 8;
                uint32_t addr = sb + SM_BHI + n * BSTR + (bk0 + koff) * 2;
                uint32_t t[4];
                ldsm_x4(t, addr);
                bh[q * 2][0] = t[0]; bh[q * 2][1] = t[1];
                bh[q * 2 + 1][0] = t[2]; bh[q * 2 + 1][1] = t[3];
                ldsm_x4(t, addr + (SM_BLO - SM_BHI));
                bl[q * 2][0] = t[0]; bl[q * 2][1] = t[1];
                bl[q * 2 + 1][0] = t[2]; bl[q * 2 + 1][1] = t[3];
            }
#pragma unroll
            for (int mf = 0; mf < 2; mf++)
#pragma unroll
                for (int nf = 0; nf < 8; nf++) {
                    mma_bf16(acc[mf][nf], ah[mf], bh[nf]);
                    mma_bf16(acc[mf][nf], ah[mf], bl[nf]);
                    mma_bf16(acc[mf][nf], al[mf], bh[nf]);
                }
        }
        if (c + 2 < 8) loadA(c + 2, (c + 2) % 3);
    }

    // ---- epilogue ----
    const int colbase = cb * 128 + warp_n * 64;
#pragma unroll
    for (int mf = 0; mf < 2; mf++) {
        int r0 = blockRow + warp_m * 32 + mf * 16 + (lane >> 2);
        int r1 = r0 + 8;
#pragma unroll
        for (int nf = 0; nf < 8; nf++) {
            int col = colbase + nf * 8 + (lane & 3) * 2;
            float b0 = bias[col], b1 = bias[col + 1];
            float o0 = acc[mf][nf][0] + b0, o1 = acc[mf][nf][1] + b1;
            float o2 = acc[mf][nf][2] + b0, o3 = acc[mf][nf][3] + b1;
            if (RELU) {
                o0 = fmaxf(o0, 0.f); o1 = fmaxf(o1, 0.f);
                o2 = fmaxf(o2, 0.f); o3 = fmaxf(o3, 0.f);
            }
            if (SPLIT) {
                unsigned short h0, l0, h1, l1;
                if (r0 < M) {
                    split1(o0, h0, l0); split1(o1, h1, l1);
                    *(uint32_t*)(Chi + (size_t)r0 * Ncols + col) = (uint32_t)h0 | ((uint32_t)h1 << 16);
                    *(uint32_t*)(Clo + (size_t)r0 * Ncols + col) = (uint32_t)l0 | ((uint32_t)l1 << 16);
                }
                if (r1 < M) {
                    split1(o2, h0, l0); split1(o3, h1, l1);
                    *(uint32_t*)(Chi + (size_t)r1 * Ncols + col) = (uint32_t)h0 | ((uint32_t)h1 << 16);
                    *(uint32_t*)(Clo + (size_t)r1 * Ncols + col) = (uint32_t)l0 | ((uint32_t)l1 << 16);
                }
            } else {
                if (r0 < M) *(float2*)(C + (size_t)r0 * Ncols + col) = make_float2(o0, o1);
                if (r1 < M) *(float2*)(C + (size_t)r1 * Ncols + col) = make_float2(o2, o3);
            }
        }
    }
}

// ---------------- log_softmax over 128-wide rows, warp per row ---------------
__global__ void logsoftmax_k(float* __restrict__ C, int M) {
    int row = blockIdx.x * 8 + (threadIdx.x >> 5);
    int lane = threadIdx.x & 31;
    if (row >= M) return;
    float4 v = *(float4*)(C + (size_t)row * 128 + lane * 4);
    float m = fmaxf(fmaxf(v.x, v.y), fmaxf(v.z, v.w));
#pragma unroll
    for (int o = 16; o; o >>= 1) m = fmaxf(m, __shfl_xor_sync(0xFFFFFFFFu, m, o));
    float s = expf(v.x - m) + expf(v.y - m) + expf(v.z - m) + expf(v.w - m);
#pragma unroll
    for (int o = 16; o; o >>= 1) s += __shfl_xor_sync(0xFFFFFFFFu, s, o);
    float lg = m + logf(s);
    v.x -= lg; v.y -= lg; v.z -= lg; v.w -= lg;
    *(float4*)(C + (size_t)row * 128 + lane * 4) = v;
}

// ---------------- host launch -------------------------------------------------
extern "C" void kernel_launch(void* const* d_in, const int* in_sizes, int n_in,
                              void* d_out, int out_size) {
    const float* x    = (const float*)d_in[0];
    const void*  ei   = d_in[1];
    const float* eps0 = (const float*)d_in[2];
    const float* W1_0 = (const float*)d_in[3];
    const float* b1_0 = (const float*)d_in[4];
    const float* W2_0 = (const float*)d_in[5];
    const float* b2_0 = (const float*)d_in[6];
    const float* eps1 = (const float*)d_in[7];
    const float* W1_1 = (const float*)d_in[8];
    const float* b1_1 = (const float*)d_in[9];
    const float* W2_1 = (const float*)d_in[10];
    const float* b2_1 = (const float*)d_in[11];
    float* out = (float*)d_out;

    int E = in_sizes[1] / 2;
    if (E > EE) E = EE;
    int M = in_sizes[0] / INC;
    if (M > NN) M = NN;

    __nv_bfloat16 *xhi, *xlo, *mhi, *mlo, *whi, *wlo;
    float* h1;
    cudaGetSymbolAddress((void**)&xhi, g_xhi);
    cudaGetSymbolAddress((void**)&xlo, g_xlo);
    cudaGetSymbolAddress((void**)&mhi, g_mhi);
    cudaGetSymbolAddress((void**)&mlo, g_mlo);
    cudaGetSymbolAddress((void**)&h1,  g_h1);
    cudaGetSymbolAddress((void**)&whi, g_wt_hi);
    cudaGetSymbolAddress((void**)&wlo, g_wt_lo);

    cudaFuncSetAttribute(gemm_mma<1, 1>, cudaFuncAttributeMaxDynamicSharedMemorySize, SM_TOTAL);
    cudaFuncSetAttribute(gemm_mma<1, 0>, cudaFuncAttributeMaxDynamicSharedMemorySize, SM_TOTAL);
    cudaFuncSetAttribute(gemm_mma<0, 0>, cudaFuncAttributeMaxDynamicSharedMemorySize, SM_TOTAL);

    const int egrid = (E + 255) / 256;
    const int ngrid = (M + 255) / 256;
    const int ggrid = (M + 7) / 8;
    const int mtiles = (M + 127) / 128;
    const dim3 grid_h(mtiles, 2);
    const dim3 grid_o(mtiles, 1);
    const int WSZ = 256 * 256;

    // ---- CSR build ----
    detect_k<<<1, 32>>>((const unsigned int*)ei);
    zero_deg_k<<<ngrid, 256>>>();
    decode_hist_k<<<egrid, 256>>>(ei, E);
    block_sum_k<<<ngrid, 256>>>(M);
    scan_bsums_k<<<1, 256>>>(ngrid);
    rowptr_k<<<ngrid, 256>>>(M);
    fill_k<<<egrid, 256>>>(E);

    // ---- weight transpose + split ----
    tw_k<<<(256 * HID + 255) / 256, 256>>>(W1_0, HID, whi + 0 * WSZ, wlo + 0 * WSZ);
    tw_k<<<(256 * HID + 255) / 256, 256>>>(W2_0, HID, whi + 1 * WSZ, wlo + 1 * WSZ);
    tw_k<<<(256 * HID + 255) / 256, 256>>>(W1_1, HID, whi + 2 * WSZ, wlo + 2 * WSZ);
    tw_k<<<(256 * OUTC + 255) / 256, 256>>>(W2_1, OUTC, whi + 3 * WSZ, wlo + 3 * WSZ);

    // ---- layer 0 ----
    gather_k<<<ggrid, 256>>>((const float4*)x, eps0, xhi, xlo, M);
    gemm_mma<1, 1><<<grid_h, 256, SM_TOTAL>>>(xhi, xlo, whi + 0 * WSZ, wlo + 0 * WSZ,
                                              b1_0, nullptr, mhi, mlo, M, HID);
    gemm_mma<1, 0><<<grid_h, 256, SM_TOTAL>>>(mhi, mlo, whi + 1 * WSZ, wlo + 1 * WSZ,
                                              b2_0, h1, nullptr, nullptr, M, HID);

    // ---- layer 1 ----
    gather_k<<<ggrid, 256>>>((const float4*)h1, eps1, xhi, xlo, M);
    gemm_mma<1, 1><<<grid_h, 256, SM_TOTAL>>>(xhi, xlo, whi + 2 * WSZ, wlo + 2 * WSZ,
                                              b1_1, nullptr, mhi, mlo, M, HID);
    gemm_mma<0, 0><<<grid_o, 256, SM_TOTAL>>>(mhi, mlo, whi + 3 * WSZ, wlo + 3 * WSZ,
                                              b2_1, out, nullptr, nullptr, M, OUTC);

    // ---- log_softmax ----
    logsoftmax_k<<<(M + 7) / 8, 256>>>(out, M);
}

// round 10
// speedup vs baseline: 3.9899x; 1.1538x over previous
#include <cuda_runtime.h>
#include <cuda_bf16.h>
#include <math.h>
#include <stdint.h>

#define NN 50000
#define EE 800000
#define INC 256
#define HID 256
#define OUTC 128

// ---------------- scratch (static device globals; no allocation) -------------
__device__ __nv_bfloat16 g_xhi[(size_t)NN * HID];  // split of gather output
__device__ __nv_bfloat16 g_xlo[(size_t)NN * HID];
__device__ __nv_bfloat16 g_mhi[(size_t)NN * HID];  // split of MLP hidden
__device__ __nv_bfloat16 g_mlo[(size_t)NN * HID];
__device__ float g_h1[(size_t)NN * HID];           // layer-0 output (fp32)
__device__ int   g_src[EE];
__device__ int   g_dst[EE];
__device__ int   g_col[EE];
__device__ int   g_deg[NN];
__device__ int   g_rowptr[NN + 1];
__device__ int   g_cursor[NN];
__device__ int   g_bsum[256];
__device__ int   g_boff[256];
__device__ int   g_is64;
// transposed + hi/lo split weights: Wt[n][k] bf16
__device__ __nv_bfloat16 g_wt_hi[4][256 * 256];
__device__ __nv_bfloat16 g_wt_lo[4][256 * 256];

// ---------------- helpers -----------------------------------------------------
__device__ __forceinline__ uint32_t smem_u32(const void* p) {
    uint32_t a;
    asm("{ .reg .u64 t; cvta.to.shared.u64 t, %1; cvt.u32.u64 %0, t; }" : "=r"(a) : "l"(p));
    return a;
}
__device__ __forceinline__ void ldsm_x4(uint32_t* r, uint32_t addr) {
    asm volatile("ldmatrix.sync.aligned.m8n8.x4.shared.b16 {%0,%1,%2,%3}, [%4];"
                 : "=r"(r[0]), "=r"(r[1]), "=r"(r[2]), "=r"(r[3]) : "r"(addr));
}
__device__ __forceinline__ void mma_bf16(float* d, const uint32_t* a, const uint32_t* b) {
    asm volatile(
        "mma.sync.aligned.m16n8k16.row.col.f32.bf16.bf16.f32 "
        "{%0,%1,%2,%3}, {%4,%5,%6,%7}, {%8,%9}, {%0,%1,%2,%3};"
        : "+f"(d[0]), "+f"(d[1]), "+f"(d[2]), "+f"(d[3])
        : "r"(a[0]), "r"(a[1]), "r"(a[2]), "r"(a[3]), "r"(b[0]), "r"(b[1]));
}
// split fp32 -> (hi, lo) bf16 pair
__device__ __forceinline__ void split1(float v, unsigned short& h, unsigned short& l) {
    __nv_bfloat16 bh = __float2bfloat16_rn(v);
    float r = v - __bfloat162float(bh);
    __nv_bfloat16 bl = __float2bfloat16_rn(r);
    h = __bfloat16_as_ushort(bh);
    l = __bfloat16_as_ushort(bl);
}
__device__ __forceinline__ void split4(float4 v, uint2& hh, uint2& ll) {
    unsigned short h[4], l[4];
    split1(v.x, h[0], l[0]); split1(v.y, h[1], l[1]);
    split1(v.z, h[2], l[2]); split1(v.w, h[3], l[3]);
    hh = make_uint2((uint32_t)h[0] | ((uint32_t)h[1] << 16),
                    (uint32_t)h[2] | ((uint32_t)h[3] << 16));
    ll = make_uint2((uint32_t)l[0] | ((uint32_t)l[1] << 16),
                    (uint32_t)l[2] | ((uint32_t)l[3] << 16));
}

// ---------------- fused zero_deg + edge dtype detection ----------------------
__global__ void detzero_k(const unsigned int* __restrict__ ei) {
    int i = blockIdx.x * blockDim.x + threadIdx.x;
    if (i < NN) g_deg[i] = 0;
    if (blockIdx.x == 0 && threadIdx.x < 32) {
        unsigned v = ei[threadIdx.x * 2 + 1];
        unsigned nz = __ballot_sync(0xFFFFFFFFu, v != 0u);
        if (threadIdx.x == 0) g_is64 = (nz == 0u) ? 1 : 0;
    }
}

__global__ void decode_hist_k(const void* __restrict__ ei, int E) {
    int i = blockIdx.x * blockDim.x + threadIdx.x;
    if (i >= E) return;
    int s, d;
    if (g_is64) {
        const long long* p = (const long long*)ei;
        s = (int)p[i];
        d = (int)p[(size_t)E + i];
    } else {
        const int* p = (const int*)ei;
        s = p[i];
        d = p[E + i];
    }
    g_src[i] = s;
    g_dst[i] = d;
    atomicAdd(&g_deg[d], 1);
}

__global__ void block_sum_k(int n) {
    __shared__ int sh[8];
    int i = blockIdx.x * 256 + threadIdx.x;
    int lane = threadIdx.x & 31;
    int wid = threadIdx.x >> 5;
    int v = (i < n) ? g_deg[i] : 0;
#pragma unroll
    for (int o = 16; o; o >>= 1) v += __shfl_down_sync(0xFFFFFFFFu, v, o);
    if (lane == 0) sh[wid] = v;
    __syncthreads();
    if (threadIdx.x == 0) {
        int s = 0;
#pragma unroll
        for (int w = 0; w < 8; w++) s += sh[w];
        g_bsum[blockIdx.x] = s;
    }
}

__global__ void scan_bsums_k(int nb) {
    __shared__ int sh[256];
    int tid = threadIdx.x;
    int v = (tid < nb) ? g_bsum[tid] : 0;
    sh[tid] = v;
    __syncthreads();
    for (int off = 1; off < 256; off <<= 1) {
        int t = (tid >= off) ? sh[tid - off] : 0;
        __syncthreads();
        sh[tid] += t;
        __syncthreads();
    }
    g_boff[tid] = sh[tid] - v;
}

__global__ void rowptr_k(int n) {
    __shared__ int sh[256];
    int i = blockIdx.x * 256 + threadIdx.x;
    int tid = threadIdx.x;
    int v = (i < n) ? g_deg[i] : 0;
    sh[tid] = v;
    __syncthreads();
    for (int off = 1; off < 256; off <<= 1) {
        int t = (tid >= off) ? sh[tid - off] : 0;
        __syncthreads();
        sh[tid] += t;
        __syncthreads();
    }
    int ex = g_boff[blockIdx.x] + sh[tid] - v;
    if (i < n) {
        g_rowptr[i] = ex;
        g_cursor[i] = ex;
        if (i == n - 1) g_rowptr[n] = ex + v;
    }
}

__global__ void fill_k(int E) {
    int i = blockIdx.x * blockDim.x + threadIdx.x;
    if (i >= E) return;
    int d = g_dst[i];
    int pos = atomicAdd(&g_cursor[d], 1);
    g_col[pos] = g_src[i];
}

// ---------------- weight transpose + hi/lo split (all 4 in one launch) -------
__global__ void tw_all_k(const float* __restrict__ W0, const float* __restrict__ W1,
                         const float* __restrict__ W2, const float* __restrict__ W3) {
    int w = blockIdx.y;
    const float* W = (w == 0) ? W0 : (w == 1) ? W1 : (w == 2) ? W2 : W3;
    int Ncols = (w == 3) ? OUTC : HID;
    int id = blockIdx.x * 256 + threadIdx.x;
    if (id >= 256 * Ncols) return;
    int k = id / Ncols, n = id % Ncols;
    float v = W[id];
    unsigned short h, l;
    split1(v, h, l);
    g_wt_hi[w][(size_t)n * 256 + k] = __ushort_as_bfloat16(h);
    g_wt_lo[w][(size_t)n * 256 + k] = __ushort_as_bfloat16(l);
}

// ---------------- gather aggregation: warp per node, split bf16 output --------
__global__ __launch_bounds__(256) void gather_k(
    const float4* __restrict__ X, const float* __restrict__ eps,
    __nv_bfloat16* __restrict__ Ohi, __nv_bfloat16* __restrict__ Olo, int M)
{
    int warp = (blockIdx.x * blockDim.x + threadIdx.x) >> 5;
    int lane = threadIdx.x & 31;
    if (warp >= M) return;
    const float alpha = 1.0f + *eps;

    float4 a0 = make_float4(0.f, 0.f, 0.f, 0.f);
    float4 a1 = make_float4(0.f, 0.f, 0.f, 0.f);

    int beg = g_rowptr[warp];
    int end = g_rowptr[warp + 1];
    int e = beg;
    for (; e + 1 < end; e += 2) {
        int s0 = __ldg(&g_col[e]);
        int s1 = __ldg(&g_col[e + 1]);
        float4 v00 = X[(size_t)s0 * 64 + lane];
        float4 v01 = X[(size_t)s0 * 64 + 32 + lane];
        float4 v10 = X[(size_t)s1 * 64 + lane];
        float4 v11 = X[(size_t)s1 * 64 + 32 + lane];
        a0.x += v00.x + v10.x; a0.y += v00.y + v10.y;
        a0.z += v00.z + v10.z; a0.w += v00.w + v10.w;
        a1.x += v01.x + v11.x; a1.y += v01.y + v11.y;
        a1.z += v01.z + v11.z; a1.w += v01.w + v11.w;
    }
    if (e < end) {
        int s0 = __ldg(&g_col[e]);
        float4 v00 = X[(size_t)s0 * 64 + lane];
        float4 v01 = X[(size_t)s0 * 64 + 32 + lane];
        a0.x += v00.x; a0.y += v00.y; a0.z += v00.z; a0.w += v00.w;
        a1.x += v01.x; a1.y += v01.y; a1.z += v01.z; a1.w += v01.w;
    }

    float4 x0 = X[(size_t)warp * 64 + lane];
    float4 x1 = X[(size_t)warp * 64 + 32 + lane];
    a0.x = fmaf(alpha, x0.x, a0.x); a0.y = fmaf(alpha, x0.y, a0.y);
    a0.z = fmaf(alpha, x0.z, a0.z); a0.w = fmaf(alpha, x0.w, a0.w);
    a1.x = fmaf(alpha, x1.x, a1.x); a1.y = fmaf(alpha, x1.y, a1.y);
    a1.z = fmaf(alpha, x1.z, a1.z); a1.w = fmaf(alpha, x1.w, a1.w);

    uint2 h0, l0, h1v, l1v;
    split4(a0, h0, l0);
    split4(a1, h1v, l1v);
    size_t base = (size_t)warp * 256 + 4 * lane;
    *(uint2*)(Ohi + base)       = h0;
    *(uint2*)(Olo + base)       = l0;
    *(uint2*)(Ohi + base + 128) = h1v;
    *(uint2*)(Olo + base + 128) = l1v;
}

// ---------------- persistent mma.sync bf16 hi/lo GEMM -------------------------
// C = act(A @ W + bias). Persistent CTAs: grid (74, y) — B loaded ONCE per CTA,
// CTA loops over row tiles (tile = blockIdx.x + k*gridDim.x). 128x128 CTA tile,
// K=256 in 8 chunks of 32, 3-stage cp.async ring. 3 passes: hh + hl + lh.
// LSM: fused log_softmax epilogue (requires Ncols==128, gridDim.y==1).
#define BSTR 528
#define ASTR 80
#define ASTAGE (2 * 128 * ASTR)
#define SM_BHI 0
#define SM_BLO (128 * BSTR)
#define SM_A   (2 * 128 * BSTR)
#define SM_TOTAL (SM_A + 3 * ASTAGE)

template <int RELU, int SPLIT, int LSM>
__global__ void __launch_bounds__(256, 1) gemm_mma(
    const __nv_bfloat16* __restrict__ Ahi, const __nv_bfloat16* __restrict__ Alo,
    const __nv_bfloat16* __restrict__ Whi, const __nv_bfloat16* __restrict__ Wlo,
    const float* __restrict__ bias,
    float* __restrict__ C,
    __nv_bfloat16* __restrict__ Chi, __nv_bfloat16* __restrict__ Clo,
    int M, int Ncols, int mtiles)
{
    extern __shared__ char smem[];
    const uint32_t sb = smem_u32(smem);
    const int tid = threadIdx.x;
    const int wid = tid >> 5, lane = tid & 31;
    const int cb = blockIdx.y;
    const int warp_m = wid & 3, warp_n = wid >> 2;

    // ---- load B hi/lo once ----
    {
        const uint4* shp = (const uint4*)(Whi + (size_t)cb * 128 * 256);
        const uint4* slp = (const uint4*)(Wlo + (size_t)cb * 128 * 256);
        for (int f = tid; f < 4096; f += 256) {
            int n = f >> 5, kc = f & 31;
            *(uint4*)(smem + SM_BHI + n * BSTR + kc * 16) = shp[n * 32 + kc];
            *(uint4*)(smem + SM_BLO + n * BSTR + kc * 16) = slp[n * 32 + kc];
        }
    }

    // bias for this thread's columns (fixed across tiles)
    const int colbase = cb * 128 + warp_n * 64;
    float bv0[8], bv1[8];
#pragma unroll
    for (int nf = 0; nf < 8; nf++) {
        int col = colbase + nf * 8 + (lane & 3) * 2;
        bv0[nf] = bias[col];
        bv1[nf] = bias[col + 1];
    }

    auto loadA = [&](int c, int st, int blockRow) {
        uint32_t base = sb + SM_A + st * ASTAGE;
#pragma unroll
        for (int j = 0; j < 2; j++) {
            int f = j * 256 + tid;
            int row = f >> 2;
            int seg = f & 3;
            int grow = blockRow + row;
            int ok = (grow < M);
            size_t off = (size_t)(ok ? grow : 0) * 256 + c * 32 + seg * 8;
            uint32_t dh = base + row * ASTR + seg * 16;
            uint32_t dl = dh + 128 * ASTR;
            int ss = ok ? 16 : 0;
            asm volatile("cp.async.ca.shared.global [%0], [%1], 16, %2;"
                         :: "r"(dh), "l"((const char*)(Ahi + off)), "r"(ss));
            asm volatile("cp.async.ca.shared.global [%0], [%1], 16, %2;"
                         :: "r"(dl), "l"((const char*)(Alo + off)), "r"(ss));
        }
        asm volatile("cp.async.commit_group;");
    };

    for (int tile = blockIdx.x; tile < mtiles; tile += gridDim.x) {
        const int blockRow = tile * 128;
        __syncthreads();    // protect stage-0/1 smem reuse across tiles

        float acc[2][8][4];
#pragma unroll
        for (int mf = 0; mf < 2; mf++)
#pragma unroll
            for (int nf = 0; nf < 8; nf++)
#pragma unroll
                for (int q = 0; q < 4; q++) acc[mf][nf][q] = 0.f;

        loadA(0, 0, blockRow);
        loadA(1, 1, blockRow);

#pragma unroll
        for (int c = 0; c < 8; c++) {
            if (c + 1 < 8) {
                asm volatile("cp.async.wait_group 1;" ::: "memory");
            } else {
                asm volatile("cp.async.wait_group 0;" ::: "memory");
            }
            __syncthreads();

            const uint32_t abase = sb + SM_A + (c % 3) * ASTAGE;
#pragma unroll
            for (int s = 0; s < 2; s++) {
                const int k0 = s * 16;
                const int bk0 = c * 32 + k0;
                uint32_t ah[2][4], al[2][4];
#pragma unroll
                for (int mf = 0; mf < 2; mf++) {
                    int row = warp_m * 32 + mf * 16 + (lane & 15);
                    uint32_t addr = abase + row * ASTR + (k0 + (lane >> 4) * 8) * 2;
                    ldsm_x4(ah[mf], addr);
                    ldsm_x4(al[mf], addr + 128 * ASTR);
                }
                uint32_t bh[8][2], bl[8][2];
#pragma unroll
                for (int q = 0; q < 4; q++) {
                    int trow = lane & 7;
                    int tsel = lane >> 3;
                    int n = warp_n * 64 + q * 16 + trow + ((tsel >> 1) * 8);
                    int koff = (tsel & 1) * 8;
                    uint32_t addr = sb + SM_BHI + n * BSTR + (bk0 + koff) * 2;
                    uint32_t t[4];
                    ldsm_x4(t, addr);
                    bh[q * 2][0] = t[0]; bh[q * 2][1] = t[1];
                    bh[q * 2 + 1][0] = t[2]; bh[q * 2 + 1][1] = t[3];
                    ldsm_x4(t, addr + (SM_BLO - SM_BHI));
                    bl[q * 2][0] = t[0]; bl[q * 2][1] = t[1];
                    bl[q * 2 + 1][0] = t[2]; bl[q * 2 + 1][1] = t[3];
                }
#pragma unroll
                for (int mf = 0; mf < 2; mf++)
#pragma unroll
                    for (int nf = 0; nf < 8; nf++) {
                        mma_bf16(acc[mf][nf], ah[mf], bh[nf]);
                        mma_bf16(acc[mf][nf], ah[mf], bl[nf]);
                        mma_bf16(acc[mf][nf], al[mf], bh[nf]);
                    }
            }
            if (c + 2 < 8) loadA(c + 2, (c + 2) % 3, blockRow);
        }

        // ---- add bias into acc ----
#pragma unroll
        for (int mf = 0; mf < 2; mf++)
#pragma unroll
            for (int nf = 0; nf < 8; nf++) {
                acc[mf][nf][0] += bv0[nf]; acc[mf][nf][1] += bv1[nf];
                acc[mf][nf][2] += bv0[nf]; acc[mf][nf][3] += bv1[nf];
            }

        if (LSM) {
            // fused log_softmax over full 128-wide rows (cb==0, warp_n splits cols)
            float* sm_max = (float*)(smem + SM_A);           // [128][2]
            float* sm_sum = (float*)(smem + SM_A + 1024);    // [128][2]
            float mx[2][2], Mv[2][2], sv[2][2];
#pragma unroll
            for (int mf = 0; mf < 2; mf++)
#pragma unroll
                for (int ri = 0; ri < 2; ri++) {
                    float m = -1e30f;
#pragma unroll
                    for (int nf = 0; nf < 8; nf++) {
                        m = fmaxf(m, acc[mf][nf][ri * 2]);
                        m = fmaxf(m, acc[mf][nf][ri * 2 + 1]);
                    }
                    m = fmaxf(m, __shfl_xor_sync(0xFFFFFFFFu, m, 1));
                    m = fmaxf(m, __shfl_xor_sync(0xFFFFFFFFu, m, 2));
                    mx[mf][ri] = m;
                }
            if ((lane & 3) == 0) {
#pragma unroll
                for (int mf = 0; mf < 2; mf++)
#pragma unroll
                    for (int ri = 0; ri < 2; ri++) {
                        int rowl = warp_m * 32 + mf * 16 + ri * 8 + (lane >> 2);
                        sm_max[rowl * 2 + warp_n] = mx[mf][ri];
                    }
            }
            __syncthreads();
#pragma unroll
            for (int mf = 0; mf < 2; mf++)
#pragma unroll
                for (int ri = 0; ri < 2; ri++) {
                    int rowl = warp_m * 32 + mf * 16 + ri * 8 + (lane >> 2);
                    float m = fmaxf(sm_max[rowl * 2], sm_max[rowl * 2 + 1]);
                    Mv[mf][ri] = m;
                    float s = 0.f;
#pragma unroll
                    for (int nf = 0; nf < 8; nf++)
                        s += expf(acc[mf][nf][ri * 2] - m) + expf(acc[mf][nf][ri * 2 + 1] - m);
                    s += __shfl_xor_sync(0xFFFFFFFFu, s, 1);
                    s += __shfl_xor_sync(0xFFFFFFFFu, s, 2);
                    sv[mf][ri] = s;
                }
            if ((lane & 3) == 0) {
#pragma unroll
                for (int mf = 0; mf < 2; mf++)
#pragma unroll
                    for (int ri = 0; ri < 2; ri++) {
                        int rowl = warp_m * 32 + mf * 16 + ri * 8 + (lane >> 2);
                        sm_sum[rowl * 2 + warp_n] = sv[mf][ri];
                    }
            }
            __syncthreads();
#pragma unroll
            for (int mf = 0; mf < 2; mf++)
#pragma unroll
                for (int ri = 0; ri < 2; ri++) {
                    int rowl = warp_m * 32 + mf * 16 + ri * 8 + (lane >> 2);
                    float S = sm_sum[rowl * 2] + sm_sum[rowl * 2 + 1];
                    float lg = Mv[mf][ri] + logf(S);
                    int row = blockRow + rowl;
                    if (row < M) {
#pragma unroll
                        for (int nf = 0; nf < 8; nf++) {
                            int col = colbase + nf * 8 + (lane & 3) * 2;
                            *(float2*)(C + (size_t)row * Ncols + col) =
                                make_float2(acc[mf][nf][ri * 2] - lg, acc[mf][nf][ri * 2 + 1] - lg);
                        }
                    }
                }
        } else {
#pragma unroll
            for (int mf = 0; mf < 2; mf++) {
                int r0 = blockRow + warp_m * 32 + mf * 16 + (lane >> 2);
                int r1 = r0 + 8;
#pragma unroll
                for (int nf = 0; nf < 8; nf++) {
                    int col = colbase + nf * 8 + (lane & 3) * 2;
                    float o0 = acc[mf][nf][0], o1 = acc[mf][nf][1];
                    float o2 = acc[mf][nf][2], o3 = acc[mf][nf][3];
                    if (RELU) {
                        o0 = fmaxf(o0, 0.f); o1 = fmaxf(o1, 0.f);
                        o2 = fmaxf(o2, 0.f); o3 = fmaxf(o3, 0.f);
                    }
                    if (SPLIT) {
                        unsigned short h0, l0, h1, l1;
                        if (r0 < M) {
                            split1(o0, h0, l0); split1(o1, h1, l1);
                            *(uint32_t*)(Chi + (size_t)r0 * Ncols + col) = (uint32_t)h0 | ((uint32_t)h1 << 16);
                            *(uint32_t*)(Clo + (size_t)r0 * Ncols + col) = (uint32_t)l0 | ((uint32_t)l1 << 16);
                        }
                        if (r1 < M) {
                            split1(o2, h0, l0); split1(o3, h1, l1);
                            *(uint32_t*)(Chi + (size_t)r1 * Ncols + col) = (uint32_t)h0 | ((uint32_t)h1 << 16);
                            *(uint32_t*)(Clo + (size_t)r1 * Ncols + col) = (uint32_t)l0 | ((uint32_t)l1 << 16);
                        }
                    } else {
                        if (r0 < M) *(float2*)(C + (size_t)r0 * Ncols + col) = make_float2(o0, o1);
                        if (r1 < M) *(float2*)(C + (size_t)r1 * Ncols + col) = make_float2(o2, o3);
                    }
                }
            }
        }
    }
}

// ---------------- host launch -------------------------------------------------
extern "C" void kernel_launch(void* const* d_in, const int* in_sizes, int n_in,
                              void* d_out, int out_size) {
    const float* x    = (const float*)d_in[0];
    const void*  ei   = d_in[1];
    const float* eps0 = (const float*)d_in[2];
    const float* W1_0 = (const float*)d_in[3];
    const float* b1_0 = (const float*)d_in[4];
    const float* W2_0 = (const float*)d_in[5];
    const float* b2_0 = (const float*)d_in[6];
    const float* eps1 = (const float*)d_in[7];
    const float* W1_1 = (const float*)d_in[8];
    const float* b1_1 = (const float*)d_in[9];
    const float* W2_1 = (const float*)d_in[10];
    const float* b2_1 = (const float*)d_in[11];
    float* out = (float*)d_out;

    int E = in_sizes[1] / 2;
    if (E > EE) E = EE;
    int M = in_sizes[0] / INC;
    if (M > NN) M = NN;

    __nv_bfloat16 *xhi, *xlo, *mhi, *mlo, *whi, *wlo;
    float* h1;
    cudaGetSymbolAddress((void**)&xhi, g_xhi);
    cudaGetSymbolAddress((void**)&xlo, g_xlo);
    cudaGetSymbolAddress((void**)&mhi, g_mhi);
    cudaGetSymbolAddress((void**)&mlo, g_mlo);
    cudaGetSymbolAddress((void**)&h1,  g_h1);
    cudaGetSymbolAddress((void**)&whi, g_wt_hi);
    cudaGetSymbolAddress((void**)&wlo, g_wt_lo);

    cudaFuncSetAttribute(gemm_mma<1, 1, 0>, cudaFuncAttributeMaxDynamicSharedMemorySize, SM_TOTAL);
    cudaFuncSetAttribute(gemm_mma<1, 0, 0>, cudaFuncAttributeMaxDynamicSharedMemorySize, SM_TOTAL);
    cudaFuncSetAttribute(gemm_mma<0, 0, 1>, cudaFuncAttributeMaxDynamicSharedMemorySize, SM_TOTAL);

    const int egrid = (E + 255) / 256;
    const int ngrid = (M + 255) / 256;
    const int ggrid = (M + 7) / 8;
    const int mtiles = (M + 127) / 128;
    const dim3 grid_h(74, 2);      // persistent: 148 CTAs = 1 full wave
    const dim3 grid_o(148, 1);
    const int WSZ = 256 * 256;

    // ---- CSR build ----
    detzero_k<<<ngrid, 256>>>((const unsigned int*)ei);
    decode_hist_k<<<egrid, 256>>>(ei, E);
    block_sum_k<<<ngrid, 256>>>(M);
    scan_bsums_k<<<1, 256>>>(ngrid);
    rowptr_k<<<ngrid, 256>>>(M);
    fill_k<<<egrid, 256>>>(E);

    // ---- weight transpose + split (single launch) ----
    tw_all_k<<<dim3(256, 4), 256>>>(W1_0, W2_0, W1_1, W2_1);

    // ---- layer 0 ----
    gather_k<<<ggrid, 256>>>((const float4*)x, eps0, xhi, xlo, M);
    gemm_mma<1, 1, 0><<<grid_h, 256, SM_TOTAL>>>(xhi, xlo, whi + 0 * WSZ, wlo + 0 * WSZ,
                                                 b1_0, nullptr, mhi, mlo, M, HID, mtiles);
    gemm_mma<1, 0, 0><<<grid_h, 256, SM_TOTAL>>>(mhi, mlo, whi + 1 * WSZ, wlo + 1 * WSZ,
                                                 b2_0, h1, nullptr, nullptr, M, HID, mtiles);

    // ---- layer 1 ----
    gather_k<<<ggrid, 256>>>((const float4*)h1, eps1, xhi, xlo, M);
    gemm_mma<1, 1, 0><<<grid_h, 256, SM_TOTAL>>>(xhi, xlo, whi + 2 * WSZ, wlo + 2 * WSZ,
                                                 b1_1, nullptr, mhi, mlo, M, HID, mtiles);
    // final GEMM with fused log_softmax
    gemm_mma<0, 0, 1><<<grid_o, 256, SM_TOTAL>>>(mhi, mlo, whi + 3 * WSZ, wlo + 3 * WSZ,
                                                 b2_1, out, nullptr, nullptr, M, OUTC, mtiles);
}